// round 1
// baseline (speedup 1.0000x reference)
#include <cuda_runtime.h>
#include <math.h>
#include <float.h>

// Problem constants
#define NPAIR 2048           // B*A
#define HD 128               // H
#define NTOK 256             // N
#define KTOP 16
#define VST 132              // padded smem row stride (floats), 16B-aligned rows
#define CFLAT 2176           // (KTOP+1)*HD

// Scratch (device globals; no allocations allowed)
__device__ float g_M[HD * HD];             // norm * Wq @ Wk^T
__device__ float g_Wmod[HD * 2 * HD];      // [128][256]: [Wmot(:, :128) | Wv @ Wmot(:,128:)^T]
__device__ float g_qeff[NPAIR * HD];
__device__ float g_X[NPAIR * 2 * HD];      // [vs | s_ve]
__device__ float g_vcf[(size_t)NPAIR * CFLAT];
__device__ float g_part[4 * NPAIR * HD];   // split-K partials

// ---------------------------------------------------------------------------
// Kernel 0: build fused weight matrices.
// grid (128, 2), block 128
// y==0: g_M[i][t] = norm * sum_j Wq[i][j] * Wk[t][j]     (block = t, thread = i)
// y==1: g_Wmod[j][0:128] = Wmot[j][0:128];
//       g_Wmod[j][128+g] = sum_h Wv[g][h] * Wmot[j][128+h]  (block = j, thread = g)
// ---------------------------------------------------------------------------
__global__ void prep_kernel(const float* __restrict__ Wq, const float* __restrict__ Wk,
                            const float* __restrict__ Wv, const float* __restrict__ Wmot) {
    __shared__ float srow[HD];
    int col = blockIdx.x;
    int t = threadIdx.x;
    if (blockIdx.y == 0) {
        srow[t] = Wk[col * HD + t];
        __syncthreads();
        const float* wq = Wq + t * HD;
        float acc = 0.f;
#pragma unroll 8
        for (int j = 0; j < HD; j++) acc += wq[j] * srow[j];
        g_M[t * HD + col] = acc * 0.08838834764831845f;  // 1/sqrt(128)
    } else {
        srow[t] = Wmot[col * 2 * HD + HD + t];
        __syncthreads();
        g_Wmod[col * 2 * HD + t] = Wmot[col * 2 * HD + t];
        const float* wv = Wv + t * HD;
        float acc = 0.f;
#pragma unroll 8
        for (int h = 0; h < HD; h++) acc += wv[h] * srow[h];
        g_Wmod[col * 2 * HD + HD + t] = acc;
    }
}

// ---------------------------------------------------------------------------
// Kernel 1: qeff[p][t] = sum_i vs[p][i] * g_M[i][t]
// grid 64, block 128; each block does 32 pairs
// ---------------------------------------------------------------------------
__global__ void qeff_kernel(const float* __restrict__ vs) {
    __shared__ float svs[32 * HD];
    int t = threadIdx.x;
    int base = blockIdx.x * 32;
    for (int k = t; k < 32 * HD; k += 128) svs[k] = vs[base * HD + k];
    __syncthreads();
    float acc[32];
#pragma unroll
    for (int p = 0; p < 32; p++) acc[p] = 0.f;
    for (int i = 0; i < HD; i++) {
        float m = g_M[i * HD + t];
#pragma unroll
        for (int p = 0; p < 32; p++) acc[p] += svs[p * HD + i] * m;
    }
#pragma unroll
    for (int p = 0; p < 32; p++) g_qeff[(base + p) * HD + t] = acc[p];
}

// ---------------------------------------------------------------------------
// Kernel 2: per-pair attention core. grid 2048, block 256, dyn smem ~135 KB.
// ---------------------------------------------------------------------------
__global__ __launch_bounds__(256) void main_kernel(const float* __restrict__ vs,
                                                   const float* __restrict__ ve,
                                                   const int* __restrict__ ved) {
    extern __shared__ float sm[];
    float* sve  = sm;                      // 256*132
    float* qs   = sve + NTOK * VST;        // 128
    float* sc   = qs + HD;                 // 256
    float* red  = sc + NTOK;               // 64
    float* part = red + 64;                // 256
    __shared__ int sidx[KTOP];
    __shared__ int sdead[NTOK];

    int tid = threadIdx.x;
    int lane = tid & 31, wid = tid >> 5;
    int p = blockIdx.x;

    // Load ve tile [256,128] into padded smem via float4
    const float4* vb = (const float4*)(ve + (size_t)p * NTOK * HD);
    for (int k = tid; k < NTOK * HD / 4; k += 256) {
        int row = k >> 5;
        int c4 = k & 31;
        float4 v = vb[k];
        *(float4*)(sve + row * VST + c4 * 4) = v;
    }
    if (tid < HD) qs[tid] = g_qeff[p * HD + tid];
    sdead[tid] = ved[p * NTOK + tid];
    __syncthreads();

    // compat[r] = qeff . ve[r]; warp-per-row, 32 rows per warp
    float q0 = qs[lane], q1 = qs[lane + 32], q2 = qs[lane + 64], q3 = qs[lane + 96];
    for (int r = wid; r < NTOK; r += 8) {
        const float* row = sve + r * VST;
        float s = row[lane] * q0 + row[lane + 32] * q1 + row[lane + 64] * q2 + row[lane + 96] * q3;
#pragma unroll
        for (int o = 16; o > 0; o >>= 1) s += __shfl_xor_sync(0xffffffffu, s, o);
        if (lane == 0) sc[r] = sdead[r] ? -INFINITY : s;
    }
    __syncthreads();

    // softmax over 256
    float v = sc[tid];
    float m = v;
#pragma unroll
    for (int o = 16; o > 0; o >>= 1) m = fmaxf(m, __shfl_xor_sync(0xffffffffu, m, o));
    if (lane == 0) red[wid] = m;
    __syncthreads();
    if (tid == 0) {
        float mm = red[0];
        for (int w = 1; w < 8; w++) mm = fmaxf(mm, red[w]);
        red[8] = mm;
    }
    __syncthreads();
    m = red[8];
    float e = (m == -INFINITY) ? 0.f : expf(v - m);  // masked v=-inf -> e=0
    float ssum = e;
#pragma unroll
    for (int o = 16; o > 0; o >>= 1) ssum += __shfl_xor_sync(0xffffffffu, ssum, o);
    if (lane == 0) red[wid] = ssum;
    __syncthreads();
    if (tid == 0) {
        float t = 0.f;
        for (int w = 0; w < 8; w++) t += red[w];
        red[9] = t;
    }
    __syncthreads();
    float tot = red[9];
    sc[tid] = (tot > 0.f) ? e / tot : 0.f;
    __syncthreads();

    // s_ve[h] = sum_n score[n]*ve[n][h]  (split n-range across 2 thread groups)
    {
        int g = tid >> 7, h = tid & 127;
        float acc = 0.f;
        const float* base = sve + (g * 128) * VST + h;
        const float* scb = sc + g * 128;
#pragma unroll 4
        for (int n = 0; n < 128; n++) acc += scb[n] * base[n * VST];
        part[tid] = acc;
    }
    __syncthreads();
    if (tid < HD) {
        float s = part[tid] + part[tid + 128];
        g_X[p * 2 * HD + HD + tid] = s;
        float vsv = vs[p * HD + tid];
        g_X[p * 2 * HD + tid] = vsv;
        g_vcf[(size_t)p * CFLAT + tid] = vsv;
    }

    // top-16 (stable: value desc, index asc) — destroys sc
    for (int k = 0; k < KTOP; k++) {
        float bv = sc[tid];
        int bi = tid;
#pragma unroll
        for (int o = 16; o > 0; o >>= 1) {
            float ov = __shfl_xor_sync(0xffffffffu, bv, o);
            int oi = __shfl_xor_sync(0xffffffffu, bi, o);
            if (ov > bv || (ov == bv && oi < bi)) { bv = ov; bi = oi; }
        }
        if (lane == 0) { red[wid] = bv; red[wid + 32] = __int_as_float(bi); }
        __syncthreads();
        if (tid == 0) {
            float bbv = red[0];
            int bbi = __float_as_int(red[32]);
            for (int w = 1; w < 8; w++) {
                float ov = red[w];
                int oi = __float_as_int(red[w + 32]);
                if (ov > bbv || (ov == bbv && oi < bbi)) { bbv = ov; bbi = oi; }
            }
            sidx[k] = bbi;
            sc[bbi] = -1.f;
        }
        __syncthreads();
    }

    // gather top-K rows into v_C_flat
    size_t ob = (size_t)p * CFLAT + HD;
    for (int j = tid; j < KTOP * HD; j += 256) {
        int k = j >> 7, h = j & 127;
        g_vcf[ob + j] = sve[sidx[k] * VST + h];
    }
}

// ---------------------------------------------------------------------------
// Kernel 3: split-K GEMM partials. out_part = A[rows,K] @ W[128,K]^T
// tile 32 rows x 128 cols, 256 threads, thread tile 4x4.
// mode 0: A = g_vcf (K=2176), W = Wext ; mode 1: A = g_X (K=256), W = g_Wmod
// grid (rows/32, nsplit)
// ---------------------------------------------------------------------------
__global__ __launch_bounds__(256) void gemm_kernel(int mode, const float* __restrict__ Wext,
                                                   int K, int kspan) {
    __shared__ float As[32 * 33];
    __shared__ float Ws[128 * 33];
    const float* A = (mode == 0) ? g_vcf : g_X;
    const float* W = (mode == 0) ? Wext : g_Wmod;

    int tid = threadIdx.x;
    int lc = tid & 31;
    int rbase = (tid >> 5) * 4;
    int br = blockIdx.x * 32;
    int k0 = blockIdx.y * kspan;
    int k1 = k0 + kspan;

    float acc[4][4];
#pragma unroll
    for (int i = 0; i < 4; i++)
#pragma unroll
        for (int j = 0; j < 4; j++) acc[i][j] = 0.f;

    for (int kk = k0; kk < k1; kk += 32) {
#pragma unroll
        for (int rep = 0; rep < 4; rep++) {
            int idx = tid + rep * 256;
            int r = idx >> 5, c = idx & 31;
            As[r * 33 + c] = A[(size_t)(br + r) * K + kk + c];
        }
#pragma unroll
        for (int rep = 0; rep < 16; rep++) {
            int idx = tid + rep * 256;
            int r = idx >> 5, c = idx & 31;
            Ws[r * 33 + c] = W[(size_t)r * K + kk + c];
        }
        __syncthreads();
#pragma unroll
        for (int t = 0; t < 32; t++) {
            float a[4], w[4];
#pragma unroll
            for (int i = 0; i < 4; i++) a[i] = As[(rbase + i) * 33 + t];
#pragma unroll
            for (int mcol = 0; mcol < 4; mcol++) w[mcol] = Ws[(lc + 32 * mcol) * 33 + t];
#pragma unroll
            for (int i = 0; i < 4; i++)
#pragma unroll
                for (int mcol = 0; mcol < 4; mcol++) acc[i][mcol] += a[i] * w[mcol];
        }
        __syncthreads();
    }

    float* pout = g_part + (size_t)blockIdx.y * NPAIR * HD;
#pragma unroll
    for (int i = 0; i < 4; i++)
#pragma unroll
        for (int mcol = 0; mcol < 4; mcol++)
            pout[(size_t)(br + rbase + i) * HD + lc + 32 * mcol] = acc[i][mcol];
}

// Reduce split-K partials + bias + relu -> out
__global__ void reduce_relu_kernel(const float* __restrict__ bias, float* __restrict__ out,
                                   int nsplit) {
    int idx = blockIdx.x * 256 + threadIdx.x;
    float s = 0.f;
    for (int sp = 0; sp < nsplit; sp++) s += g_part[(size_t)sp * NPAIR * HD + idx];
    s += bias[idx & (HD - 1)];
    out[idx] = fmaxf(s, 0.f);
}

// ---------------------------------------------------------------------------
extern "C" void kernel_launch(void* const* d_in, const int* in_sizes, int n_in,
                              void* d_out, int out_size) {
    const float* vs   = (const float*)d_in[0];
    const float* ve   = (const float*)d_in[1];
    const int*   ved  = (const int*)d_in[2];
    const float* Wq   = (const float*)d_in[3];
    const float* Wk   = (const float*)d_in[4];
    const float* Wv   = (const float*)d_in[5];
    const float* Wmot = (const float*)d_in[6];
    const float* bmot = (const float*)d_in[7];
    const float* Wfwd = (const float*)d_in[8];
    const float* bfwd = (const float*)d_in[9];
    float* out = (float*)d_out;  // [v_C_final (2048*128) | v_M_final (2048*128)]

    const int SMEM1 = (NTOK * VST + HD + NTOK + 64 + NTOK) * 4;
    cudaFuncSetAttribute(main_kernel, cudaFuncAttributeMaxDynamicSharedMemorySize, SMEM1);

    prep_kernel<<<dim3(128, 2), 128>>>(Wq, Wk, Wv, Wmot);
    qeff_kernel<<<64, 128>>>(vs);
    main_kernel<<<NPAIR, 256, SMEM1>>>(vs, ve, ved);

    // GEMM 1: v_C_flat [2048,2176] @ W_fwd^T, split-K 4 (kspan 544)
    gemm_kernel<<<dim3(NPAIR / 32, 4), 256>>>(0, Wfwd, CFLAT, 544);
    reduce_relu_kernel<<<NPAIR * HD / 256, 256>>>(bfwd, out, 4);

    // GEMM 2: X [2048,256] @ Wmod^T, no split
    gemm_kernel<<<dim3(NPAIR / 32, 1), 256>>>(1, nullptr, 2 * HD, 2 * HD);
    reduce_relu_kernel<<<NPAIR * HD / 256, 256>>>(bmot, out + NPAIR * HD, 1);
}

// round 2
// speedup vs baseline: 1.0025x; 1.0025x over previous
#include <cuda_runtime.h>
#include <math.h>
#include <float.h>

// Problem constants
#define NPAIR 2048           // B*A
#define HD 128               // H
#define NTOK 256             // N
#define KTOP 16
#define VST 132              // padded smem row stride (floats), 16B-aligned rows
#define CFLAT 2176           // (KTOP+1)*HD

// Scratch (device globals; no allocations allowed)
__device__ float g_M[HD * HD];             // norm * Wq @ Wk^T
__device__ float g_Wmod[HD * 2 * HD];      // [128][256]: [Wmot(:, :128) | Wv @ Wmot(:,128:)^T]
__device__ float g_qeff[NPAIR * HD];
__device__ float g_X[NPAIR * 2 * HD];      // [vs | s_ve]
__device__ float g_vcf[(size_t)NPAIR * CFLAT];
__device__ float g_part[4 * NPAIR * HD];   // split-K partials

// ---------------------------------------------------------------------------
// Kernel 0: build fused weight matrices.
// grid (128, 2), block 128
// y==0: g_M[i][t] = norm * sum_j Wq[i][j] * Wk[t][j]     (block = t, thread = i)
// y==1: g_Wmod[j][0:128] = Wmot[j][0:128];
//       g_Wmod[j][128+g] = sum_h Wv[g][h] * Wmot[j][128+h]  (block = j, thread = g)
// ---------------------------------------------------------------------------
__global__ void prep_kernel(const float* __restrict__ Wq, const float* __restrict__ Wk,
                            const float* __restrict__ Wv, const float* __restrict__ Wmot) {
    __shared__ float srow[HD];
    int col = blockIdx.x;
    int t = threadIdx.x;
    if (blockIdx.y == 0) {
        srow[t] = Wk[col * HD + t];
        __syncthreads();
        const float* wq = Wq + t * HD;
        float acc = 0.f;
#pragma unroll 8
        for (int j = 0; j < HD; j++) acc += wq[j] * srow[j];
        g_M[t * HD + col] = acc * 0.08838834764831845f;  // 1/sqrt(128)
    } else {
        srow[t] = Wmot[col * 2 * HD + HD + t];
        __syncthreads();
        g_Wmod[col * 2 * HD + t] = Wmot[col * 2 * HD + t];
        const float* wv = Wv + t * HD;
        float acc = 0.f;
#pragma unroll 8
        for (int h = 0; h < HD; h++) acc += wv[h] * srow[h];
        g_Wmod[col * 2 * HD + HD + t] = acc;
    }
}

// ---------------------------------------------------------------------------
// Kernel 1: qeff[p][t] = sum_i vs[p][i] * g_M[i][t]
// grid 64, block 128; each block does 32 pairs
// ---------------------------------------------------------------------------
__global__ void qeff_kernel(const float* __restrict__ vs) {
    __shared__ float svs[32 * HD];
    int t = threadIdx.x;
    int base = blockIdx.x * 32;
    for (int k = t; k < 32 * HD; k += 128) svs[k] = vs[base * HD + k];
    __syncthreads();
    float acc[32];
#pragma unroll
    for (int p = 0; p < 32; p++) acc[p] = 0.f;
    for (int i = 0; i < HD; i++) {
        float m = g_M[i * HD + t];
#pragma unroll
        for (int p = 0; p < 32; p++) acc[p] += svs[p * HD + i] * m;
    }
#pragma unroll
    for (int p = 0; p < 32; p++) g_qeff[(base + p) * HD + t] = acc[p];
}

// ---------------------------------------------------------------------------
// Kernel 2: per-pair attention core. grid 2048, block 256, dyn smem ~135 KB.
// ---------------------------------------------------------------------------
__global__ __launch_bounds__(256) void main_kernel(const float* __restrict__ vs,
                                                   const float* __restrict__ ve,
                                                   const int* __restrict__ ved) {
    extern __shared__ float sm[];
    float* sve  = sm;                      // 256*132
    float* qs   = sve + NTOK * VST;        // 128
    float* sc   = qs + HD;                 // 256
    float* red  = sc + NTOK;               // 64
    float* part = red + 64;                // 256
    __shared__ int sidx[KTOP];
    __shared__ int sdead[NTOK];

    int tid = threadIdx.x;
    int lane = tid & 31, wid = tid >> 5;
    int p = blockIdx.x;

    // Load ve tile [256,128] into padded smem via float4
    const float4* vb = (const float4*)(ve + (size_t)p * NTOK * HD);
    for (int k = tid; k < NTOK * HD / 4; k += 256) {
        int row = k >> 5;
        int c4 = k & 31;
        float4 v = vb[k];
        *(float4*)(sve + row * VST + c4 * 4) = v;
    }
    if (tid < HD) qs[tid] = g_qeff[p * HD + tid];
    sdead[tid] = ved[p * NTOK + tid];
    __syncthreads();

    // compat[r] = qeff . ve[r]; warp-per-row, 32 rows per warp
    float q0 = qs[lane], q1 = qs[lane + 32], q2 = qs[lane + 64], q3 = qs[lane + 96];
    for (int r = wid; r < NTOK; r += 8) {
        const float* row = sve + r * VST;
        float s = row[lane] * q0 + row[lane + 32] * q1 + row[lane + 64] * q2 + row[lane + 96] * q3;
#pragma unroll
        for (int o = 16; o > 0; o >>= 1) s += __shfl_xor_sync(0xffffffffu, s, o);
        if (lane == 0) sc[r] = sdead[r] ? -INFINITY : s;
    }
    __syncthreads();

    // softmax over 256
    float v = sc[tid];
    float m = v;
#pragma unroll
    for (int o = 16; o > 0; o >>= 1) m = fmaxf(m, __shfl_xor_sync(0xffffffffu, m, o));
    if (lane == 0) red[wid] = m;
    __syncthreads();
    if (tid == 0) {
        float mm = red[0];
        for (int w = 1; w < 8; w++) mm = fmaxf(mm, red[w]);
        red[8] = mm;
    }
    __syncthreads();
    m = red[8];
    float e = (m == -INFINITY) ? 0.f : expf(v - m);  // masked v=-inf -> e=0
    float ssum = e;
#pragma unroll
    for (int o = 16; o > 0; o >>= 1) ssum += __shfl_xor_sync(0xffffffffu, ssum, o);
    if (lane == 0) red[wid] = ssum;
    __syncthreads();
    if (tid == 0) {
        float t = 0.f;
        for (int w = 0; w < 8; w++) t += red[w];
        red[9] = t;
    }
    __syncthreads();
    float tot = red[9];
    sc[tid] = (tot > 0.f) ? e / tot : 0.f;
    __syncthreads();

    // s_ve[h] = sum_n score[n]*ve[n][h]  (split n-range across 2 thread groups)
    {
        int g = tid >> 7, h = tid & 127;
        float acc = 0.f;
        const float* base = sve + (g * 128) * VST + h;
        const float* scb = sc + g * 128;
#pragma unroll 4
        for (int n = 0; n < 128; n++) acc += scb[n] * base[n * VST];
        part[tid] = acc;
    }
    __syncthreads();
    if (tid < HD) {
        float s = part[tid] + part[tid + 128];
        g_X[p * 2 * HD + HD + tid] = s;
        float vsv = vs[p * HD + tid];
        g_X[p * 2 * HD + tid] = vsv;
        g_vcf[(size_t)p * CFLAT + tid] = vsv;
    }

    // top-16 (stable: value desc, index asc) — destroys sc
    for (int k = 0; k < KTOP; k++) {
        float bv = sc[tid];
        int bi = tid;
#pragma unroll
        for (int o = 16; o > 0; o >>= 1) {
            float ov = __shfl_xor_sync(0xffffffffu, bv, o);
            int oi = __shfl_xor_sync(0xffffffffu, bi, o);
            if (ov > bv || (ov == bv && oi < bi)) { bv = ov; bi = oi; }
        }
        if (lane == 0) { red[wid] = bv; red[wid + 32] = __int_as_float(bi); }
        __syncthreads();
        if (tid == 0) {
            float bbv = red[0];
            int bbi = __float_as_int(red[32]);
            for (int w = 1; w < 8; w++) {
                float ov = red[w];
                int oi = __float_as_int(red[w + 32]);
                if (ov > bbv || (ov == bbv && oi < bbi)) { bbv = ov; bbi = oi; }
            }
            sidx[k] = bbi;
            sc[bbi] = -1.f;
        }
        __syncthreads();
    }

    // gather top-K rows into v_C_flat
    size_t ob = (size_t)p * CFLAT + HD;
    for (int j = tid; j < KTOP * HD; j += 256) {
        int k = j >> 7, h = j & 127;
        g_vcf[ob + j] = sve[sidx[k] * VST + h];
    }
}

// ---------------------------------------------------------------------------
// Kernel 3: split-K GEMM partials. out_part = A[rows,K] @ W[128,K]^T
// tile 32 rows x 128 cols, 256 threads, thread tile 4x4.
// mode 0: A = g_vcf (K=2176), W = Wext ; mode 1: A = g_X (K=256), W = g_Wmod
// grid (rows/32, nsplit)
// ---------------------------------------------------------------------------
__global__ __launch_bounds__(256) void gemm_kernel(int mode, const float* __restrict__ Wext,
                                                   int K, int kspan) {
    __shared__ float As[32 * 33];
    __shared__ float Ws[128 * 33];
    const float* A = (mode == 0) ? g_vcf : g_X;
    const float* W = (mode == 0) ? Wext : g_Wmod;

    int tid = threadIdx.x;
    int lc = tid & 31;
    int rbase = (tid >> 5) * 4;
    int br = blockIdx.x * 32;
    int k0 = blockIdx.y * kspan;
    int k1 = k0 + kspan;

    float acc[4][4];
#pragma unroll
    for (int i = 0; i < 4; i++)
#pragma unroll
        for (int j = 0; j < 4; j++) acc[i][j] = 0.f;

    for (int kk = k0; kk < k1; kk += 32) {
#pragma unroll
        for (int rep = 0; rep < 4; rep++) {
            int idx = tid + rep * 256;
            int r = idx >> 5, c = idx & 31;
            As[r * 33 + c] = A[(size_t)(br + r) * K + kk + c];
        }
#pragma unroll
        for (int rep = 0; rep < 16; rep++) {
            int idx = tid + rep * 256;
            int r = idx >> 5, c = idx & 31;
            Ws[r * 33 + c] = W[(size_t)r * K + kk + c];
        }
        __syncthreads();
#pragma unroll
        for (int t = 0; t < 32; t++) {
            float a[4], w[4];
#pragma unroll
            for (int i = 0; i < 4; i++) a[i] = As[(rbase + i) * 33 + t];
#pragma unroll
            for (int mcol = 0; mcol < 4; mcol++) w[mcol] = Ws[(lc + 32 * mcol) * 33 + t];
#pragma unroll
            for (int i = 0; i < 4; i++)
#pragma unroll
                for (int mcol = 0; mcol < 4; mcol++) acc[i][mcol] += a[i] * w[mcol];
        }
        __syncthreads();
    }

    float* pout = g_part + (size_t)blockIdx.y * NPAIR * HD;
#pragma unroll
    for (int i = 0; i < 4; i++)
#pragma unroll
        for (int mcol = 0; mcol < 4; mcol++)
            pout[(size_t)(br + rbase + i) * HD + lc + 32 * mcol] = acc[i][mcol];
}

// Reduce split-K partials + bias + relu -> out
__global__ void reduce_relu_kernel(const float* __restrict__ bias, float* __restrict__ out,
                                   int nsplit) {
    int idx = blockIdx.x * 256 + threadIdx.x;
    float s = 0.f;
    for (int sp = 0; sp < nsplit; sp++) s += g_part[(size_t)sp * NPAIR * HD + idx];
    s += bias[idx & (HD - 1)];
    out[idx] = fmaxf(s, 0.f);
}

// ---------------------------------------------------------------------------
extern "C" void kernel_launch(void* const* d_in, const int* in_sizes, int n_in,
                              void* d_out, int out_size) {
    const float* vs   = (const float*)d_in[0];
    const float* ve   = (const float*)d_in[1];
    const int*   ved  = (const int*)d_in[2];
    const float* Wq   = (const float*)d_in[3];
    const float* Wk   = (const float*)d_in[4];
    const float* Wv   = (const float*)d_in[5];
    const float* Wmot = (const float*)d_in[6];
    const float* bmot = (const float*)d_in[7];
    const float* Wfwd = (const float*)d_in[8];
    const float* bfwd = (const float*)d_in[9];
    float* out = (float*)d_out;  // [v_C_final (2048*128) | v_M_final (2048*128)]

    const int SMEM1 = (NTOK * VST + HD + NTOK + 64 + NTOK) * 4;
    cudaFuncSetAttribute(main_kernel, cudaFuncAttributeMaxDynamicSharedMemorySize, SMEM1);

    prep_kernel<<<dim3(128, 2), 128>>>(Wq, Wk, Wv, Wmot);
    qeff_kernel<<<64, 128>>>(vs);
    main_kernel<<<NPAIR, 256, SMEM1>>>(vs, ve, ved);

    // GEMM 1: v_C_flat [2048,2176] @ W_fwd^T, split-K 4 (kspan 544)
    gemm_kernel<<<dim3(NPAIR / 32, 4), 256>>>(0, Wfwd, CFLAT, 544);
    reduce_relu_kernel<<<NPAIR * HD / 256, 256>>>(bfwd, out, 4);

    // GEMM 2: X [2048,256] @ Wmod^T, no split
    gemm_kernel<<<dim3(NPAIR / 32, 1), 256>>>(1, nullptr, 2 * HD, 2 * HD);
    reduce_relu_kernel<<<NPAIR * HD / 256, 256>>>(bmot, out + NPAIR * HD, 1);
}

// round 3
// speedup vs baseline: 1.8038x; 1.7992x over previous
#include <cuda_runtime.h>
#include <math.h>
#include <float.h>

// Problem constants
#define NPAIR 2048           // B*A
#define HD 128               // H
#define NTOK 256             // N
#define KTOP 16
#define NSPLIT1 17           // 2176 / 128

// Scratch (device globals; no allocations allowed)
__device__ float g_M[HD * HD];                    // norm * Wq @ Wk^T
__device__ float g_Wmod[HD * 2 * HD];             // [Wmot(:, :128) | Wv @ Wmot(:,128:)^T]
__device__ float g_qeff[NPAIR * HD];
__device__ float g_X[NPAIR * 2 * HD];             // [vs | s_ve]
__device__ int   g_idx[NPAIR * KTOP];             // top-16 indices
__device__ float g_part[NSPLIT1 * NPAIR * HD];    // split-K partials

// ---------------------------------------------------------------------------
// Kernel 0: build fused weight matrices. grid (128, 2), block 128
// ---------------------------------------------------------------------------
__global__ void prep_kernel(const float* __restrict__ Wq, const float* __restrict__ Wk,
                            const float* __restrict__ Wv, const float* __restrict__ Wmot) {
    __shared__ float srow[HD];
    int col = blockIdx.x;
    int t = threadIdx.x;
    if (blockIdx.y == 0) {
        srow[t] = Wk[col * HD + t];
        __syncthreads();
        const float* wq = Wq + t * HD;
        float acc = 0.f;
#pragma unroll 8
        for (int j = 0; j < HD; j++) acc += wq[j] * srow[j];
        g_M[t * HD + col] = acc * 0.08838834764831845f;  // 1/sqrt(128)
    } else {
        srow[t] = Wmot[col * 2 * HD + HD + t];
        __syncthreads();
        g_Wmod[col * 2 * HD + t] = Wmot[col * 2 * HD + t];
        const float* wv = Wv + t * HD;
        float acc = 0.f;
#pragma unroll 8
        for (int h = 0; h < HD; h++) acc += wv[h] * srow[h];
        g_Wmod[col * 2 * HD + HD + t] = acc;
    }
}

// ---------------------------------------------------------------------------
// Kernel 1: qeff[p][t] = sum_i vs[p][i] * g_M[i][t]. grid 64, block 128.
// ---------------------------------------------------------------------------
__global__ void qeff_kernel(const float* __restrict__ vs) {
    __shared__ float svs[32 * HD];
    int t = threadIdx.x;
    int base = blockIdx.x * 32;
    for (int k = t; k < 32 * HD; k += 128) svs[k] = vs[base * HD + k];
    __syncthreads();
    float acc[32];
#pragma unroll
    for (int p = 0; p < 32; p++) acc[p] = 0.f;
    for (int i = 0; i < HD; i++) {
        float m = g_M[i * HD + t];
#pragma unroll
        for (int p = 0; p < 32; p++) acc[p] += svs[p * HD + i] * m;
    }
#pragma unroll
    for (int p = 0; p < 32; p++) g_qeff[(base + p) * HD + t] = acc[p];
}

// ---------------------------------------------------------------------------
// Kernel 2: attention core, streaming (no 128KB smem stage).
// grid 2048, block 256, ~3.3 KB smem -> high occupancy, DRAM-BW bound.
// Phase 1: compat = ve . qeff (warp-per-row, float4, stream from gmem/DRAM)
// Phase 2: masked softmax (block reduce)
// Phase 3: s_ve = score . ve (re-read ve; hits L2: wave working set << 126MB)
// Phase 4: top-16 in a single warp on register-resident scores (shfl only)
// ---------------------------------------------------------------------------
__global__ __launch_bounds__(256) void attn_kernel(const float* __restrict__ vs,
                                                   const float* __restrict__ ve,
                                                   const int* __restrict__ ved) {
    __shared__ float sc[NTOK];
    __shared__ float red[64];
    __shared__ float part[256];
    __shared__ int sdead[NTOK];

    int tid = threadIdx.x;
    int lane = tid & 31, wid = tid >> 5;
    int p = blockIdx.x;

    sdead[tid] = ved[p * NTOK + tid];
    float4 q = *(const float4*)(g_qeff + p * HD + lane * 4);
    const float4* vb = (const float4*)(ve + (size_t)p * NTOK * HD);
    __syncthreads();

    // Phase 1: compat. Warp wid owns rows [wid*32, wid*32+32), unroll 2 for MLP.
    for (int i = 0; i < 32; i += 2) {
        int r = (wid << 5) + i;
        float4 a = vb[r * 32 + lane];
        float4 b = vb[(r + 1) * 32 + lane];
        float s0 = a.x * q.x + a.y * q.y + a.z * q.z + a.w * q.w;
        float s1 = b.x * q.x + b.y * q.y + b.z * q.z + b.w * q.w;
#pragma unroll
        for (int o = 16; o > 0; o >>= 1) {
            s0 += __shfl_xor_sync(0xffffffffu, s0, o);
            s1 += __shfl_xor_sync(0xffffffffu, s1, o);
        }
        if (lane == 0) {
            sc[r]     = sdead[r]     ? -INFINITY : s0;
            sc[r + 1] = sdead[r + 1] ? -INFINITY : s1;
        }
    }
    __syncthreads();

    // Phase 2: softmax over 256
    float v = sc[tid];
    float m = v;
#pragma unroll
    for (int o = 16; o > 0; o >>= 1) m = fmaxf(m, __shfl_xor_sync(0xffffffffu, m, o));
    if (lane == 0) red[wid] = m;
    __syncthreads();
    if (tid == 0) {
        float mm = red[0];
        for (int w = 1; w < 8; w++) mm = fmaxf(mm, red[w]);
        red[8] = mm;
    }
    __syncthreads();
    m = red[8];
    float e = (m == -INFINITY) ? 0.f : expf(v - m);
    float ssum = e;
#pragma unroll
    for (int o = 16; o > 0; o >>= 1) ssum += __shfl_xor_sync(0xffffffffu, ssum, o);
    if (lane == 0) red[wid] = ssum;
    __syncthreads();
    if (tid == 0) {
        float t = 0.f;
        for (int w = 0; w < 8; w++) t += red[w];
        red[9] = t;
    }
    __syncthreads();
    float tot = red[9];
    sc[tid] = (tot > 0.f) ? e / tot : 0.f;
    __syncthreads();

    // Phase 3: s_ve[h] = sum_n score[n]*ve[n][h]; second pass over ve (L2 hits).
    {
        int g = tid >> 7, h = tid & 127;
        const float* base = ve + (size_t)p * NTOK * HD + (size_t)(g * 128) * HD + h;
        const float* sp = sc + g * 128;
        float a0 = 0.f, a1 = 0.f, a2 = 0.f, a3 = 0.f;
        for (int n = 0; n < 128; n += 4) {
            a0 += sp[n]     * base[(size_t)n * HD];
            a1 += sp[n + 1] * base[(size_t)(n + 1) * HD];
            a2 += sp[n + 2] * base[(size_t)(n + 2) * HD];
            a3 += sp[n + 3] * base[(size_t)(n + 3) * HD];
        }
        part[tid] = (a0 + a1) + (a2 + a3);
    }
    __syncthreads();
    if (tid < HD) {
        g_X[p * 2 * HD + tid] = vs[p * HD + tid];
        g_X[p * 2 * HD + HD + tid] = part[tid] + part[tid + 128];
    }

    // Phase 4: top-16 (stable: value desc, index asc), warp 0 only, registers.
    if (wid == 0) {
        float val[8];
#pragma unroll
        for (int j = 0; j < 8; j++) val[j] = sc[lane + (j << 5)];
        for (int k = 0; k < KTOP; k++) {
            float bv = val[0];
            int bj = 0;
#pragma unroll
            for (int j = 1; j < 8; j++)
                if (val[j] > bv) { bv = val[j]; bj = j; }  // strict > keeps lowest index
            int bi = (bj << 5) + lane;
#pragma unroll
            for (int o = 16; o > 0; o >>= 1) {
                float ov = __shfl_xor_sync(0xffffffffu, bv, o);
                int oi = __shfl_xor_sync(0xffffffffu, bi, o);
                if (ov > bv || (ov == bv && oi < bi)) { bv = ov; bi = oi; }
            }
            if (lane == 0) g_idx[p * KTOP + k] = bi;
            if ((bi & 31) == lane) val[bi >> 5] = -1.f;  // scores in [0,1]
        }
    }
}

// ---------------------------------------------------------------------------
// Kernel 3: register-tiled GEMM with fused top-k gather.
// out_part[s] = A_s[64,128] @ W[:, 128s:128s+128]^T  per (M-block, split)
// mode 0: A_s rows = vs (s=0) or gathered ve[p][idx[p][s-1]] (s>=1), W=Wfwd
// mode 1: A_s rows = g_X[p][128s:...], W=g_Wmod
// block 256, tile 64x128x128, thread tile 8x4, k-major smem.
// ---------------------------------------------------------------------------
__global__ __launch_bounds__(256) void gemm_kernel(const float* __restrict__ W,
                                                   const float* __restrict__ ve,
                                                   const float* __restrict__ vs,
                                                   int Kstride, int mode) {
    extern __shared__ float smg[];
    float* As = smg;             // [128 k][64 r]
    float* Ws = smg + 128 * 64;  // [128 k][128 col]

    int tid = threadIdx.x;
    int br = blockIdx.x * 64;
    int s = blockIdx.y;
    int k0 = s * 128;
    const float* Wp = (mode == 0) ? W : g_Wmod;

    // Load W tile transposed to k-major
    {
        int col = tid >> 1;
        int kb = (tid & 1) * 64;
        const float* wsrc = Wp + (size_t)col * Kstride + k0 + kb;
#pragma unroll
        for (int j = 0; j < 16; j++) {
            float4 f = *(const float4*)(wsrc + j * 4);
            int k = kb + j * 4;
            Ws[k * 128 + col] = f.x;
            Ws[(k + 1) * 128 + col] = f.y;
            Ws[(k + 2) * 128 + col] = f.z;
            Ws[(k + 3) * 128 + col] = f.w;
        }
    }
    // Load A tile (gathered) transposed to k-major
    {
        int r = tid >> 2;
        int p = br + r;
        const float4* src;
        if (mode == 0) {
            src = (s == 0)
                ? (const float4*)(vs + (size_t)p * HD)
                : (const float4*)(ve + ((size_t)p * NTOK + g_idx[p * KTOP + s - 1]) * HD);
        } else {
            src = (const float4*)(g_X + (size_t)p * 2 * HD + k0);
        }
#pragma unroll
        for (int j = 0; j < 8; j++) {
            int c4 = (tid & 3) + 4 * j;
            float4 f = src[c4];
            int k = c4 * 4;
            As[k * 64 + r] = f.x;
            As[(k + 1) * 64 + r] = f.y;
            As[(k + 2) * 64 + r] = f.z;
            As[(k + 3) * 64 + r] = f.w;
        }
    }
    __syncthreads();

    int rg = tid >> 5;   // warp id -> rows rg*8..rg*8+7 (broadcast within warp)
    int cg = tid & 31;   // lane    -> cols cg*4..cg*4+3
    float acc[8][4];
#pragma unroll
    for (int i = 0; i < 8; i++)
#pragma unroll
        for (int j = 0; j < 4; j++) acc[i][j] = 0.f;

#pragma unroll 4
    for (int t = 0; t < 128; t++) {
        float4 a0 = *(const float4*)(As + t * 64 + rg * 8);
        float4 a1 = *(const float4*)(As + t * 64 + rg * 8 + 4);
        float4 w  = *(const float4*)(Ws + t * 128 + cg * 4);
        float av[8] = {a0.x, a0.y, a0.z, a0.w, a1.x, a1.y, a1.z, a1.w};
        float wv[4] = {w.x, w.y, w.z, w.w};
#pragma unroll
        for (int i = 0; i < 8; i++)
#pragma unroll
            for (int j = 0; j < 4; j++) acc[i][j] += av[i] * wv[j];
    }

    float* pout = g_part + (size_t)s * NPAIR * HD + (size_t)br * HD;
#pragma unroll
    for (int i = 0; i < 8; i++) {
        float4 o = make_float4(acc[i][0], acc[i][1], acc[i][2], acc[i][3]);
        *(float4*)(pout + (rg * 8 + i) * HD + cg * 4) = o;
    }
}

// Reduce split-K partials + bias + relu -> out
__global__ void reduce_relu_kernel(const float* __restrict__ bias, float* __restrict__ out,
                                   int nsplit) {
    int idx = blockIdx.x * 256 + threadIdx.x;
    float s = 0.f;
    for (int sp = 0; sp < nsplit; sp++) s += g_part[(size_t)sp * NPAIR * HD + idx];
    s += bias[idx & (HD - 1)];
    out[idx] = fmaxf(s, 0.f);
}

// ---------------------------------------------------------------------------
extern "C" void kernel_launch(void* const* d_in, const int* in_sizes, int n_in,
                              void* d_out, int out_size) {
    const float* vs   = (const float*)d_in[0];
    const float* ve   = (const float*)d_in[1];
    const int*   ved  = (const int*)d_in[2];
    const float* Wq   = (const float*)d_in[3];
    const float* Wk   = (const float*)d_in[4];
    const float* Wv   = (const float*)d_in[5];
    const float* Wmot = (const float*)d_in[6];
    const float* bmot = (const float*)d_in[7];
    const float* Wfwd = (const float*)d_in[8];
    const float* bfwd = (const float*)d_in[9];
    float* out = (float*)d_out;  // [v_C_final (2048*128) | v_M_final (2048*128)]

    const int SMEM_G = (128 * 64 + 128 * 128) * 4;  // 96 KB
    cudaFuncSetAttribute(gemm_kernel, cudaFuncAttributeMaxDynamicSharedMemorySize, SMEM_G);

    prep_kernel<<<dim3(128, 2), 128>>>(Wq, Wk, Wv, Wmot);
    qeff_kernel<<<64, 128>>>(vs);
    attn_kernel<<<NPAIR, 256>>>(vs, ve, ved);

    // GEMM 1: [vs | gathered ve rows] @ W_fwd^T, split-K 17 (one ve row / split)
    gemm_kernel<<<dim3(NPAIR / 64, NSPLIT1), 256, SMEM_G>>>(Wfwd, ve, vs, 2176, 0);
    reduce_relu_kernel<<<NPAIR * HD / 256, 256>>>(bfwd, out, NSPLIT1);

    // GEMM 2: X [2048,256] @ Wmod^T, split-K 2
    gemm_kernel<<<dim3(NPAIR / 64, 2), 256, SMEM_G>>>(nullptr, ve, vs, 2 * HD, 1);
    reduce_relu_kernel<<<NPAIR * HD / 256, 256>>>(bmot, out + NPAIR * HD, 2);
}

// round 4
// speedup vs baseline: 1.9231x; 1.0661x over previous
#include <cuda_runtime.h>
#include <math.h>
#include <float.h>

// Problem constants
#define NPAIR 2048           // B*A
#define HD 128               // H
#define NTOK 256             // N
#define KTOP 16
#define NSPLIT1 17           // 2176 / 128

// Scratch (device globals; no allocations allowed)
__device__ float g_M[HD * HD];                    // norm * Wq @ Wk^T
__device__ float g_Wmod[HD * 2 * HD];             // [Wmot(:, :128) | Wv @ Wmot(:,128:)^T]
__device__ float g_qeff[NPAIR * HD];
__device__ float g_X[NPAIR * 2 * HD];             // [vs | s_ve]
__device__ int   g_idx[NPAIR * KTOP];             // top-16 indices
__device__ float g_part[NSPLIT1 * NPAIR * HD];    // split-K partials

// ---------------------------------------------------------------------------
// Kernel 0: build fused weight matrices. grid (128, 2), block 128
// ---------------------------------------------------------------------------
__global__ void prep_kernel(const float* __restrict__ Wq, const float* __restrict__ Wk,
                            const float* __restrict__ Wv, const float* __restrict__ Wmot) {
    __shared__ float srow[HD];
    int col = blockIdx.x;
    int t = threadIdx.x;
    if (blockIdx.y == 0) {
        srow[t] = Wk[col * HD + t];
        __syncthreads();
        const float* wq = Wq + t * HD;
        float acc = 0.f;
#pragma unroll 8
        for (int j = 0; j < HD; j++) acc += wq[j] * srow[j];
        g_M[t * HD + col] = acc * 0.08838834764831845f;  // 1/sqrt(128)
    } else {
        srow[t] = Wmot[col * 2 * HD + HD + t];
        __syncthreads();
        g_Wmod[col * 2 * HD + t] = Wmot[col * 2 * HD + t];
        const float* wv = Wv + t * HD;
        float acc = 0.f;
#pragma unroll 8
        for (int h = 0; h < HD; h++) acc += wv[h] * srow[h];
        g_Wmod[col * 2 * HD + HD + t] = acc;
    }
}

// ---------------------------------------------------------------------------
// Kernel 1: qeff[p][t] = sum_i vs[p][i] * g_M[i][t]. grid 64, block 128.
// ---------------------------------------------------------------------------
__global__ void qeff_kernel(const float* __restrict__ vs) {
    __shared__ float svs[32 * HD];
    int t = threadIdx.x;
    int base = blockIdx.x * 32;
    for (int k = t; k < 32 * HD; k += 128) svs[k] = vs[base * HD + k];
    __syncthreads();
    float acc[32];
#pragma unroll
    for (int p = 0; p < 32; p++) acc[p] = 0.f;
    for (int i = 0; i < HD; i++) {
        float m = g_M[i * HD + t];
#pragma unroll
        for (int p = 0; p < 32; p++) acc[p] += svs[p * HD + i] * m;
    }
#pragma unroll
    for (int p = 0; p < 32; p++) g_qeff[(base + p) * HD + t] = acc[p];
}

// ---------------------------------------------------------------------------
// Kernel 2: ONE-PASS flash attention core. grid 2048, block 256.
// Per warp (32 rows): compute compat, maintain online softmax state
// (m, l, acc[128] as float4/lane) while ve streams through ONCE.
// Merge 8 warps via smem, then top-16 on scores (warp 0, registers).
// ---------------------------------------------------------------------------
__global__ __launch_bounds__(256) void attn_kernel(const float* __restrict__ vs,
                                                   const float* __restrict__ ve,
                                                   const int* __restrict__ ved) {
    __shared__ float sc[NTOK];          // compat -> scores
    __shared__ float accsh[8 * 132];    // per-warp rescaled accumulators (padded)
    __shared__ float mred[8];
    __shared__ float lred[8];

    int tid = threadIdx.x;
    int lane = tid & 31, wid = tid >> 5;
    int p = blockIdx.x;

    int dead = ved[p * NTOK + (wid << 5) + lane];   // flag of row (wid*32+lane)
    float4 q = *(const float4*)(g_qeff + p * HD + lane * 4);
    const float4* vb = (const float4*)(ve + (size_t)p * NTOK * HD);

    float m = -INFINITY, l = 0.f;
    float4 acc = make_float4(0.f, 0.f, 0.f, 0.f);

    for (int i = 0; i < 32; i += 2) {
        int r = (wid << 5) + i;
        float4 a0 = vb[r * 32 + lane];
        float4 a1 = vb[(r + 1) * 32 + lane];
        float c0 = a0.x * q.x + a0.y * q.y + a0.z * q.z + a0.w * q.w;
        float c1 = a1.x * q.x + a1.y * q.y + a1.z * q.z + a1.w * q.w;
#pragma unroll
        for (int o = 16; o > 0; o >>= 1) {
            c0 += __shfl_xor_sync(0xffffffffu, c0, o);
            c1 += __shfl_xor_sync(0xffffffffu, c1, o);
        }
        if (__shfl_sync(0xffffffffu, dead, i))     c0 = -INFINITY;
        if (__shfl_sync(0xffffffffu, dead, i + 1)) c1 = -INFINITY;
        if (lane == 0) { sc[r] = c0; sc[r + 1] = c1; }
        float mn = fmaxf(m, fmaxf(c0, c1));
        if (mn != -INFINITY) {
            float scl = expf(m - mn);    // m=-inf -> 0
            float e0 = expf(c0 - mn);    // c=-inf -> 0
            float e1 = expf(c1 - mn);
            l = l * scl + e0 + e1;
            acc.x = acc.x * scl + e0 * a0.x + e1 * a1.x;
            acc.y = acc.y * scl + e0 * a0.y + e1 * a1.y;
            acc.z = acc.z * scl + e0 * a0.z + e1 * a1.z;
            acc.w = acc.w * scl + e0 * a0.w + e1 * a1.w;
            m = mn;
        }
    }

    if (lane == 0) mred[wid] = m;
    __syncthreads();
    float gm = mred[0];
#pragma unroll
    for (int w = 1; w < 8; w++) gm = fmaxf(gm, mred[w]);
    float gs = (m == -INFINITY) ? 0.f : expf(m - gm);
    l *= gs;
    if (lane == 0) lred[wid] = l;
    {
        float4 av = make_float4(acc.x * gs, acc.y * gs, acc.z * gs, acc.w * gs);
        *(float4*)(accsh + wid * 132 + lane * 4) = av;
    }
    __syncthreads();

    float Lt = lred[0];
#pragma unroll
    for (int w = 1; w < 8; w++) Lt += lred[w];

    if (tid < HD) {
        float ssum = 0.f;
#pragma unroll
        for (int w = 0; w < 8; w++) ssum += accsh[w * 132 + tid];
        g_X[p * 2 * HD + tid] = vs[p * HD + tid];
        g_X[p * 2 * HD + HD + tid] = (Lt > 0.f) ? ssum / Lt : 0.f;
    }

    // compat -> score (same fp32 pipeline as reference two-pass softmax)
    float cmp = sc[tid];
    float sco = (gm == -INFINITY) ? 0.f : expf(cmp - gm);
    sc[tid] = (Lt > 0.f) ? sco / Lt : 0.f;
    __syncthreads();

    // top-16 (stable: value desc, index asc), warp 0, register-resident
    if (wid == 0) {
        float val[8];
#pragma unroll
        for (int j = 0; j < 8; j++) val[j] = sc[lane + (j << 5)];
        for (int k = 0; k < KTOP; k++) {
            float bv = val[0];
            int bj = 0;
#pragma unroll
            for (int j = 1; j < 8; j++)
                if (val[j] > bv) { bv = val[j]; bj = j; }  // strict > keeps lowest index
            int bi = (bj << 5) + lane;
#pragma unroll
            for (int o = 16; o > 0; o >>= 1) {
                float ov = __shfl_xor_sync(0xffffffffu, bv, o);
                int oi = __shfl_xor_sync(0xffffffffu, bi, o);
                if (ov > bv || (ov == bv && oi < bi)) { bv = ov; bi = oi; }
            }
            if (lane == 0) g_idx[p * KTOP + k] = bi;
            if ((bi & 31) == lane) val[bi >> 5] = -1.f;  // scores in [0,1]
        }
    }
}

// ---------------------------------------------------------------------------
// Kernel 3: register-tiled GEMM with fused top-k gather.
// Block tile BM x 128 (N) x 128 (K per split), k-chunks of 64 in smem.
// Thread tile TM x 8. block 256. BM = 16*TM.
// mode 0: A rows = vs (s=0) or gathered ve[p][idx[p][s-1]] (s>=1), W=Wfwd
// mode 1: A rows = g_X[p][128s : 128s+128], W=g_Wmod
// ---------------------------------------------------------------------------
template<int BM, int TM>
__global__ __launch_bounds__(256, 2) void gemm_kernel(const float* __restrict__ W,
                                                      const float* __restrict__ ve,
                                                      const float* __restrict__ vs,
                                                      int Kstride, int mode) {
    extern __shared__ float smg[];
    float* As = smg;             // [64][BM] k-major
    float* Ws = smg + 64 * BM;   // [64][128] k-major

    int tid = threadIdx.x;
    int br = blockIdx.x * BM;
    int s = blockIdx.y;
    int k0 = s * 128;
    const float* Wp = (mode == 0) ? W : g_Wmod;

    constexpr int TPR = 256 / BM;       // threads per A row (2 or 4)
    constexpr int ASPAN = 64 / TPR;     // k floats per thread per chunk
    int ar = tid / TPR;
    int akq = (tid % TPR) * ASPAN;
    const float* aptr;
    {
        int p = br + ar;
        if (mode == 0) {
            aptr = (s == 0) ? vs + (size_t)p * HD
                            : ve + ((size_t)p * NTOK + g_idx[p * KTOP + s - 1]) * HD;
        } else {
            aptr = g_X + (size_t)p * 2 * HD + k0;
        }
    }
    int wn = tid >> 1;
    int wkq = (tid & 1) * 32;
    const float* wptr = Wp + (size_t)wn * Kstride + k0;

    int tx = tid & 15;        // N-dir: cols tx*8 .. tx*8+7
    int ty = tid >> 4;        // M-dir: rows ty*TM .. ty*TM+TM-1
    float acc[TM][8];
#pragma unroll
    for (int i = 0; i < TM; i++)
#pragma unroll
        for (int j = 0; j < 8; j++) acc[i][j] = 0.f;

    for (int c = 0; c < 2; c++) {
        int kb = c * 64;
        // Load W chunk transposed to k-major
#pragma unroll
        for (int j = 0; j < 8; j++) {
            float4 f = *(const float4*)(wptr + kb + wkq + j * 4);
            int k = wkq + j * 4;
            Ws[k * 128 + wn] = f.x;
            Ws[(k + 1) * 128 + wn] = f.y;
            Ws[(k + 2) * 128 + wn] = f.z;
            Ws[(k + 3) * 128 + wn] = f.w;
        }
        // Load A chunk (gathered rows) transposed to k-major
#pragma unroll
        for (int j = 0; j < ASPAN / 4; j++) {
            float4 f = *(const float4*)(aptr + kb + akq + j * 4);
            int k = akq + j * 4;
            As[k * BM + ar] = f.x;
            As[(k + 1) * BM + ar] = f.y;
            As[(k + 2) * BM + ar] = f.z;
            As[(k + 3) * BM + ar] = f.w;
        }
        __syncthreads();

#pragma unroll 8
        for (int k = 0; k < 64; k++) {
            float av[TM], wv[8];
#pragma unroll
            for (int u = 0; u < TM / 4; u++) {
                float4 f = *(const float4*)(As + k * BM + ty * TM + u * 4);
                av[u * 4] = f.x; av[u * 4 + 1] = f.y; av[u * 4 + 2] = f.z; av[u * 4 + 3] = f.w;
            }
            {
                float4 f0 = *(const float4*)(Ws + k * 128 + tx * 8);
                float4 f1 = *(const float4*)(Ws + k * 128 + tx * 8 + 4);
                wv[0] = f0.x; wv[1] = f0.y; wv[2] = f0.z; wv[3] = f0.w;
                wv[4] = f1.x; wv[5] = f1.y; wv[6] = f1.z; wv[7] = f1.w;
            }
#pragma unroll
            for (int i = 0; i < TM; i++)
#pragma unroll
                for (int j = 0; j < 8; j++) acc[i][j] += av[i] * wv[j];
        }
        __syncthreads();
    }

    float* pout = g_part + (size_t)s * NPAIR * HD + (size_t)br * HD;
#pragma unroll
    for (int i = 0; i < TM; i++) {
        int row = ty * TM + i;
        *(float4*)(pout + row * HD + tx * 8) =
            make_float4(acc[i][0], acc[i][1], acc[i][2], acc[i][3]);
        *(float4*)(pout + row * HD + tx * 8 + 4) =
            make_float4(acc[i][4], acc[i][5], acc[i][6], acc[i][7]);
    }
}

// Reduce split-K partials + bias + relu -> out
__global__ void reduce_relu_kernel(const float* __restrict__ bias, float* __restrict__ out,
                                   int nsplit) {
    int idx = blockIdx.x * 256 + threadIdx.x;
    float s = 0.f;
    for (int sp = 0; sp < nsplit; sp++) s += g_part[(size_t)sp * NPAIR * HD + idx];
    s += bias[idx & (HD - 1)];
    out[idx] = fmaxf(s, 0.f);
}

// ---------------------------------------------------------------------------
extern "C" void kernel_launch(void* const* d_in, const int* in_sizes, int n_in,
                              void* d_out, int out_size) {
    const float* vs   = (const float*)d_in[0];
    const float* ve   = (const float*)d_in[1];
    const int*   ved  = (const int*)d_in[2];
    const float* Wq   = (const float*)d_in[3];
    const float* Wk   = (const float*)d_in[4];
    const float* Wv   = (const float*)d_in[5];
    const float* Wmot = (const float*)d_in[6];
    const float* bmot = (const float*)d_in[7];
    const float* Wfwd = (const float*)d_in[8];
    const float* bfwd = (const float*)d_in[9];
    float* out = (float*)d_out;  // [v_C_final (2048*128) | v_M_final (2048*128)]

    const int SMEM_G1 = (64 * 128 + 64 * 128) * 4;  // 64 KB (BM=128)
    const int SMEM_G2 = (64 * 64 + 64 * 128) * 4;   // 48 KB (BM=64)
    cudaFuncSetAttribute(gemm_kernel<128, 8>, cudaFuncAttributeMaxDynamicSharedMemorySize, SMEM_G1);
    cudaFuncSetAttribute(gemm_kernel<64, 4>, cudaFuncAttributeMaxDynamicSharedMemorySize, SMEM_G2);

    prep_kernel<<<dim3(128, 2), 128>>>(Wq, Wk, Wv, Wmot);
    qeff_kernel<<<64, 128>>>(vs);
    attn_kernel<<<NPAIR, 256>>>(vs, ve, ved);

    // GEMM 1: [vs | gathered ve rows] @ W_fwd^T, split-K 17 (one ve row / split)
    gemm_kernel<128, 8><<<dim3(NPAIR / 128, NSPLIT1), 256, SMEM_G1>>>(Wfwd, ve, vs, 2176, 0);
    reduce_relu_kernel<<<NPAIR * HD / 256, 256>>>(bfwd, out, NSPLIT1);

    // GEMM 2: X [2048,256] @ Wmod^T, split-K 2
    gemm_kernel<64, 4><<<dim3(NPAIR / 64, 2), 256, SMEM_G2>>>(nullptr, ve, vs, 2 * HD, 1);
    reduce_relu_kernel<<<NPAIR * HD / 256, 256>>>(bmot, out + NPAIR * HD, 2);
}

// round 6
// speedup vs baseline: 1.9667x; 1.0227x over previous
#include <cuda_runtime.h>
#include <math.h>
#include <float.h>

// Problem constants
#define NPAIR 2048           // B*A
#define HD 128               // H
#define NTOK 256             // N
#define KTOP 16
#define NSPLIT1 17           // 2176 / 128

// Scratch (device globals; no allocations allowed)
__device__ float g_M[HD * HD];                    // norm * Wq @ Wk^T
__device__ float g_Wmod[HD * 2 * HD];             // [Wmot(:, :128) | Wv @ Wmot(:,128:)^T]
__device__ float g_qeff[NPAIR * HD];
__device__ float g_X[NPAIR * 2 * HD];             // [vs | s_ve]
__device__ int   g_idx[NPAIR * KTOP];             // top-16 indices
__device__ float g_part[NSPLIT1 * NPAIR * HD];    // split-K partials

// ---------------------------------------------------------------------------
// Kernel 0: build fused weight matrices. grid (128, 2), block 128
// ---------------------------------------------------------------------------
__global__ void prep_kernel(const float* __restrict__ Wq, const float* __restrict__ Wk,
                            const float* __restrict__ Wv, const float* __restrict__ Wmot) {
    __shared__ float srow[HD];
    int col = blockIdx.x;
    int t = threadIdx.x;
    if (blockIdx.y == 0) {
        srow[t] = Wk[col * HD + t];
        __syncthreads();
        const float* wq = Wq + t * HD;
        float acc = 0.f;
#pragma unroll 8
        for (int j = 0; j < HD; j++) acc += wq[j] * srow[j];
        g_M[t * HD + col] = acc * 0.08838834764831845f;  // 1/sqrt(128)
    } else {
        srow[t] = Wmot[col * 2 * HD + HD + t];
        __syncthreads();
        g_Wmod[col * 2 * HD + t] = Wmot[col * 2 * HD + t];
        const float* wv = Wv + t * HD;
        float acc = 0.f;
#pragma unroll 8
        for (int h = 0; h < HD; h++) acc += wv[h] * srow[h];
        g_Wmod[col * 2 * HD + HD + t] = acc;
    }
}

// ---------------------------------------------------------------------------
// Kernel 1: qeff[p][t] = sum_i vs[p][i] * g_M[i][t]. grid 64, block 128.
// ---------------------------------------------------------------------------
__global__ void qeff_kernel(const float* __restrict__ vs) {
    __shared__ float svs[32 * HD];
    int t = threadIdx.x;
    int base = blockIdx.x * 32;
    for (int k = t; k < 32 * HD; k += 128) svs[k] = vs[base * HD + k];
    __syncthreads();
    float acc[32];
#pragma unroll
    for (int p = 0; p < 32; p++) acc[p] = 0.f;
    for (int i = 0; i < HD; i++) {
        float m = g_M[i * HD + t];
#pragma unroll
        for (int p = 0; p < 32; p++) acc[p] += svs[p * HD + i] * m;
    }
#pragma unroll
    for (int p = 0; p < 32; p++) g_qeff[(base + p) * HD + t] = acc[p];
}

// ---------------------------------------------------------------------------
// Kernel 2: one-pass attention, NO online max (compat values are O(1), so
// exp(c) directly is safe and mathematically identical to softmax).
// grid 2048, block 256. Per warp: 32 rows. 4 rows/step, prefetch next 4
// -> 8 outstanding LDG.128 per warp, no serial chain across iterations.
// ---------------------------------------------------------------------------
__global__ __launch_bounds__(256) void attn_kernel(const float* __restrict__ vs,
                                                   const float* __restrict__ ve,
                                                   const int* __restrict__ ved) {
    __shared__ float sc[NTOK];          // exp(compat) (unnormalized scores)
    __shared__ float accsh[8 * 132];    // per-warp accumulators (padded)
    __shared__ float lred[8];

    int tid = threadIdx.x;
    int lane = tid & 31, wid = tid >> 5;
    int p = blockIdx.x;

    int dead = ved[p * NTOK + (wid << 5) + lane];   // flag of row wid*32+lane
    float4 q = *(const float4*)(g_qeff + p * HD + lane * 4);
    const float4* vb = (const float4*)(ve + (size_t)p * NTOK * HD) + (wid << 10) + lane;

    float l = 0.f;
    float4 acc = make_float4(0.f, 0.f, 0.f, 0.f);

    float4 a0 = vb[0], a1 = vb[32], a2 = vb[64], a3 = vb[96];
    for (int i = 0; i < 32; i += 4) {
        float4 n0, n1, n2, n3;
        if (i < 28) {
            const float4* nb = vb + ((i + 4) << 5);
            n0 = nb[0]; n1 = nb[32]; n2 = nb[64]; n3 = nb[96];
        }
        float c0 = a0.x * q.x + a0.y * q.y + a0.z * q.z + a0.w * q.w;
        float c1 = a1.x * q.x + a1.y * q.y + a1.z * q.z + a1.w * q.w;
        float c2 = a2.x * q.x + a2.y * q.y + a2.z * q.z + a2.w * q.w;
        float c3 = a3.x * q.x + a3.y * q.y + a3.z * q.z + a3.w * q.w;
#pragma unroll
        for (int o = 16; o > 0; o >>= 1) {
            c0 += __shfl_xor_sync(0xffffffffu, c0, o);
            c1 += __shfl_xor_sync(0xffffffffu, c1, o);
            c2 += __shfl_xor_sync(0xffffffffu, c2, o);
            c3 += __shfl_xor_sync(0xffffffffu, c3, o);
        }
        float e0 = __shfl_sync(0xffffffffu, dead, i)     ? 0.f : expf(c0);
        float e1 = __shfl_sync(0xffffffffu, dead, i + 1) ? 0.f : expf(c1);
        float e2 = __shfl_sync(0xffffffffu, dead, i + 2) ? 0.f : expf(c2);
        float e3 = __shfl_sync(0xffffffffu, dead, i + 3) ? 0.f : expf(c3);
        if (lane == 0) {
            int r = (wid << 5) + i;
            sc[r] = e0; sc[r + 1] = e1; sc[r + 2] = e2; sc[r + 3] = e3;
        }
        l += (e0 + e1) + (e2 + e3);
        acc.x += e0 * a0.x + e1 * a1.x + e2 * a2.x + e3 * a3.x;
        acc.y += e0 * a0.y + e1 * a1.y + e2 * a2.y + e3 * a3.y;
        acc.z += e0 * a0.z + e1 * a1.z + e2 * a2.z + e3 * a3.z;
        acc.w += e0 * a0.w + e1 * a1.w + e2 * a2.w + e3 * a3.w;
        a0 = n0; a1 = n1; a2 = n2; a3 = n3;
    }

    if (lane == 0) lred[wid] = l;
    *(float4*)(accsh + wid * 132 + lane * 4) = acc;
    __syncthreads();

    float Lt = lred[0];
#pragma unroll
    for (int w = 1; w < 8; w++) Lt += lred[w];

    if (tid < HD) {
        float ssum = 0.f;
#pragma unroll
        for (int w = 0; w < 8; w++) ssum += accsh[w * 132 + tid];
        g_X[p * 2 * HD + tid] = vs[p * HD + tid];
        g_X[p * 2 * HD + HD + tid] = (Lt > 0.f) ? ssum / Lt : 0.f;
    }
    __syncthreads();

    // top-16 on unnormalized e (monotone with score): stable desc, index asc.
    // All-masked pair: all e = 0 -> picks indices 0..15 (matches jax argsort).
    if (wid == 0) {
        float val[8];
#pragma unroll
        for (int j = 0; j < 8; j++) val[j] = sc[lane + (j << 5)];
        for (int k = 0; k < KTOP; k++) {
            float bv = val[0];
            int bj = 0;
#pragma unroll
            for (int j = 1; j < 8; j++)
                if (val[j] > bv) { bv = val[j]; bj = j; }  // strict > keeps lowest index
            int bi = (bj << 5) + lane;
#pragma unroll
            for (int o = 16; o > 0; o >>= 1) {
                float ov = __shfl_xor_sync(0xffffffffu, bv, o);
                int oi = __shfl_xor_sync(0xffffffffu, bi, o);
                if (ov > bv || (ov == bv && oi < bi)) { bv = ov; bi = oi; }
            }
            if (lane == 0) g_idx[p * KTOP + k] = bi;
            if ((bi & 31) == lane) val[bi >> 5] = -1.f;  // e >= 0
        }
    }
}

// ---------------------------------------------------------------------------
// Kernel 3: register-tiled GEMM with fused top-k gather.
// Block tile BM x 128 (N) x 128 (K per split), k-chunks of 64 in smem.
// Thread tile TM x 8. block 256. BM = 16*TM.
// mode 0: A rows = vs (s=0) or gathered ve[p][idx[p][s-1]] (s>=1), W=Wfwd
// mode 1: A rows = g_X[p][128s : 128s+128], W=g_Wmod
// ---------------------------------------------------------------------------
template<int BM, int TM>
__global__ __launch_bounds__(256, 2) void gemm_kernel(const float* __restrict__ W,
                                                      const float* __restrict__ ve,
                                                      const float* __restrict__ vs,
                                                      int Kstride, int mode) {
    extern __shared__ float smg[];
    float* As = smg;             // [64][BM] k-major
    float* Ws = smg + 64 * BM;   // [64][128] k-major

    int tid = threadIdx.x;
    int br = blockIdx.x * BM;
    int s = blockIdx.y;
    int k0 = s * 128;
    const float* Wp = (mode == 0) ? W : g_Wmod;

    constexpr int TPR = 256 / BM;       // threads per A row (2 or 4)
    constexpr int ASPAN = 64 / TPR;     // k floats per thread per chunk
    int ar = tid / TPR;
    int akq = (tid % TPR) * ASPAN;
    const float* aptr;
    {
        int p = br + ar;
        if (mode == 0) {
            aptr = (s == 0) ? vs + (size_t)p * HD
                            : ve + ((size_t)p * NTOK + g_idx[p * KTOP + s - 1]) * HD;
        } else {
            aptr = g_X + (size_t)p * 2 * HD + k0;
        }
    }
    int wn = tid >> 1;
    int wkq = (tid & 1) * 32;
    const float* wptr = Wp + (size_t)wn * Kstride + k0;

    int tx = tid & 15;        // N-dir: cols tx*8 .. tx*8+7
    int ty = tid >> 4;        // M-dir: rows ty*TM .. ty*TM+TM-1
    float acc[TM][8];
#pragma unroll
    for (int i = 0; i < TM; i++)
#pragma unroll
        for (int j = 0; j < 8; j++) acc[i][j] = 0.f;

    for (int c = 0; c < 2; c++) {
        int kb = c * 64;
        // Load W chunk transposed to k-major
#pragma unroll
        for (int j = 0; j < 8; j++) {
            float4 f = *(const float4*)(wptr + kb + wkq + j * 4);
            int k = wkq + j * 4;
            Ws[k * 128 + wn] = f.x;
            Ws[(k + 1) * 128 + wn] = f.y;
            Ws[(k + 2) * 128 + wn] = f.z;
            Ws[(k + 3) * 128 + wn] = f.w;
        }
        // Load A chunk (gathered rows) transposed to k-major
#pragma unroll
        for (int j = 0; j < ASPAN / 4; j++) {
            float4 f = *(const float4*)(aptr + kb + akq + j * 4);
            int k = akq + j * 4;
            As[k * BM + ar] = f.x;
            As[(k + 1) * BM + ar] = f.y;
            As[(k + 2) * BM + ar] = f.z;
            As[(k + 3) * BM + ar] = f.w;
        }
        __syncthreads();

#pragma unroll 8
        for (int k = 0; k < 64; k++) {
            float av[TM], wv[8];
#pragma unroll
            for (int u = 0; u < TM / 4; u++) {
                float4 f = *(const float4*)(As + k * BM + ty * TM + u * 4);
                av[u * 4] = f.x; av[u * 4 + 1] = f.y; av[u * 4 + 2] = f.z; av[u * 4 + 3] = f.w;
            }
            {
                float4 f0 = *(const float4*)(Ws + k * 128 + tx * 8);
                float4 f1 = *(const float4*)(Ws + k * 128 + tx * 8 + 4);
                wv[0] = f0.x; wv[1] = f0.y; wv[2] = f0.z; wv[3] = f0.w;
                wv[4] = f1.x; wv[5] = f1.y; wv[6] = f1.z; wv[7] = f1.w;
            }
#pragma unroll
            for (int i = 0; i < TM; i++)
#pragma unroll
                for (int j = 0; j < 8; j++) acc[i][j] += av[i] * wv[j];
        }
        __syncthreads();
    }

    float* pout = g_part + (size_t)s * NPAIR * HD + (size_t)br * HD;
#pragma unroll
    for (int i = 0; i < TM; i++) {
        int row = ty * TM + i;
        *(float4*)(pout + row * HD + tx * 8) =
            make_float4(acc[i][0], acc[i][1], acc[i][2], acc[i][3]);
        *(float4*)(pout + row * HD + tx * 8 + 4) =
            make_float4(acc[i][4], acc[i][5], acc[i][6], acc[i][7]);
    }
}

// Reduce split-K partials + bias + relu -> out
__global__ void reduce_relu_kernel(const float* __restrict__ bias, float* __restrict__ out,
                                   int nsplit) {
    int idx = blockIdx.x * 256 + threadIdx.x;
    float s = 0.f;
    for (int sp = 0; sp < nsplit; sp++) s += g_part[(size_t)sp * NPAIR * HD + idx];
    s += bias[idx & (HD - 1)];
    out[idx] = fmaxf(s, 0.f);
}

// ---------------------------------------------------------------------------
extern "C" void kernel_launch(void* const* d_in, const int* in_sizes, int n_in,
                              void* d_out, int out_size) {
    const float* vs   = (const float*)d_in[0];
    const float* ve   = (const float*)d_in[1];
    const int*   ved  = (const int*)d_in[2];
    const float* Wq   = (const float*)d_in[3];
    const float* Wk   = (const float*)d_in[4];
    const float* Wv   = (const float*)d_in[5];
    const float* Wmot = (const float*)d_in[6];
    const float* bmot = (const float*)d_in[7];
    const float* Wfwd = (const float*)d_in[8];
    const float* bfwd = (const float*)d_in[9];
    float* out = (float*)d_out;  // [v_C_final (2048*128) | v_M_final (2048*128)]

    const int SMEM_G1 = (64 * 128 + 64 * 128) * 4;  // 64 KB (BM=128)
    const int SMEM_G2 = (64 * 64 + 64 * 128) * 4;   // 48 KB (BM=64)
    cudaFuncSetAttribute(gemm_kernel<128, 8>, cudaFuncAttributeMaxDynamicSharedMemorySize, SMEM_G1);
    cudaFuncSetAttribute(gemm_kernel<64, 4>, cudaFuncAttributeMaxDynamicSharedMemorySize, SMEM_G2);

    prep_kernel<<<dim3(128, 2), 128>>>(Wq, Wk, Wv, Wmot);
    qeff_kernel<<<64, 128>>>(vs);
    attn_kernel<<<NPAIR, 256>>>(vs, ve, ved);

    // GEMM 1: [vs | gathered ve rows] @ W_fwd^T, split-K 17 (one ve row / split)
    gemm_kernel<128, 8><<<dim3(NPAIR / 128, NSPLIT1), 256, SMEM_G1>>>(Wfwd, ve, vs, 2176, 0);
    reduce_relu_kernel<<<NPAIR * HD / 256, 256>>>(bfwd, out, NSPLIT1);

    // GEMM 2: X [2048,256] @ Wmod^T, split-K 2
    gemm_kernel<64, 4><<<dim3(NPAIR / 64, 2), 256, SMEM_G2>>>(nullptr, ve, vs, 2 * HD, 1);
    reduce_relu_kernel<<<NPAIR * HD / 256, 256>>>(bmot, out + NPAIR * HD, 2);
}

// round 7
// speedup vs baseline: 2.3837x; 1.2120x over previous
#include <cuda_runtime.h>
#include <math.h>
#include <float.h>
#include <stdint.h>

// Problem constants
#define NPAIR 2048           // B*A
#define HD 128               // H
#define NTOK 256             // N
#define KTOP 16
#define NSPLIT1 17           // 2176 / 128
#define NSLOTS 19            // 17 (gemm1) + 2 (gemm2)

// Scratch (device globals; no allocations allowed)
__device__ float g_M[HD * HD];                    // norm * Wq @ Wk^T
__device__ float g_Wmod[HD * 2 * HD];             // [Wmot(:, :128) | Wv @ Wmot(:,128:)^T]
__device__ float g_qeff[NPAIR * HD];
__device__ float g_X[NPAIR * 2 * HD];             // [vs | s_ve]
__device__ int   g_idx[NPAIR * KTOP];             // top-16 indices
__device__ float g_part[(size_t)NSLOTS * NPAIR * HD];  // split-K partials

__device__ __forceinline__ uint32_t smem_u32(const void* p) {
    uint32_t a;
    asm("{ .reg .u64 t; cvta.to.shared.u64 t, %1; cvt.u32.u64 %0, t; }" : "=r"(a) : "l"(p));
    return a;
}

// ---------------------------------------------------------------------------
// Kernel 0: build fused weight matrices. grid (128, 2), block 128
// ---------------------------------------------------------------------------
__global__ void prep_kernel(const float* __restrict__ Wq, const float* __restrict__ Wk,
                            const float* __restrict__ Wv, const float* __restrict__ Wmot) {
    __shared__ float srow[HD];
    int col = blockIdx.x;
    int t = threadIdx.x;
    if (blockIdx.y == 0) {
        srow[t] = Wk[col * HD + t];
        __syncthreads();
        const float* wq = Wq + t * HD;
        float acc = 0.f;
#pragma unroll 8
        for (int j = 0; j < HD; j++) acc += wq[j] * srow[j];
        g_M[t * HD + col] = acc * 0.08838834764831845f;  // 1/sqrt(128)
    } else {
        srow[t] = Wmot[col * 2 * HD + HD + t];
        __syncthreads();
        g_Wmod[col * 2 * HD + t] = Wmot[col * 2 * HD + t];
        const float* wv = Wv + t * HD;
        float acc = 0.f;
#pragma unroll 8
        for (int h = 0; h < HD; h++) acc += wv[h] * srow[h];
        g_Wmod[col * 2 * HD + HD + t] = acc;
    }
}

// ---------------------------------------------------------------------------
// Kernel 1: qeff[p][t] = sum_i vs[p][i] * g_M[i][t].
// grid 256, block 128; 8 pairs per block (wide parallelism, unrolled loads).
// ---------------------------------------------------------------------------
__global__ void qeff_kernel(const float* __restrict__ vs) {
    __shared__ float svs[8 * HD];
    int t = threadIdx.x;
    int base = blockIdx.x * 8;
    for (int k = t; k < 8 * HD; k += 128) svs[k] = vs[base * HD + k];
    __syncthreads();
    float acc[8];
#pragma unroll
    for (int p = 0; p < 8; p++) acc[p] = 0.f;
#pragma unroll 4
    for (int i = 0; i < HD; i++) {
        float m = g_M[i * HD + t];
#pragma unroll
        for (int p = 0; p < 8; p++) acc[p] += svs[p * HD + i] * m;
    }
#pragma unroll
    for (int p = 0; p < 8; p++) g_qeff[(base + p) * HD + t] = acc[p];
}

// ---------------------------------------------------------------------------
// Kernel 2: one-pass attention with cp.async triple-buffered smem pipeline.
// grid 2048, block 256, dyn smem 48 KB (3 x 16KB chunks of 32 rows).
// No online max (compat is O(1); exp(c) directly == softmax identity).
// ---------------------------------------------------------------------------
__global__ __launch_bounds__(256) void attn_kernel(const float* __restrict__ vs,
                                                   const float* __restrict__ ve,
                                                   const int* __restrict__ ved) {
    extern __shared__ float sve[];      // [3][4096] floats = 48 KB
    __shared__ float sc[NTOK];          // exp(compat)
    __shared__ float accsh[8 * 132];
    __shared__ float lred[8];
    __shared__ int sdead[NTOK];

    int tid = threadIdx.x;
    int lane = tid & 31, wid = tid >> 5;
    int p = blockIdx.x;

    sdead[tid] = ved[p * NTOK + tid];
    float4 q = *(const float4*)(g_qeff + p * HD + lane * 4);
    const float4* vb = (const float4*)(ve + (size_t)p * NTOK * HD);
    uint32_t sbase = smem_u32(sve);

    // issue chunk c: 32 rows = 1024 float4; each thread copies 4 (16B cp.async)
    auto issue = [&](int c) {
        uint32_t d = sbase + (uint32_t)(c % 3) * 16384 + (uint32_t)tid * 16;
        const float4* src = vb + c * 1024 + tid;
#pragma unroll
        for (int j = 0; j < 4; j++) {
            asm volatile("cp.async.cg.shared.global [%0], [%1], 16;"
                         :: "r"(d + j * 4096), "l"(src + j * 256));
        }
        asm volatile("cp.async.commit_group;" ::: "memory");
    };

    issue(0);
    issue(1);

    float l = 0.f;
    float4 acc = make_float4(0.f, 0.f, 0.f, 0.f);

    for (int c = 0; c < 8; c++) {
        if (c < 7) asm volatile("cp.async.wait_group 1;" ::: "memory");
        else       asm volatile("cp.async.wait_group 0;" ::: "memory");
        __syncthreads();
        if (c < 6) issue(c + 2);

        const float* bb = sve + (c % 3) * 4096 + (wid * 4) * 128 + lane * 4;
        float4 a0 = *(const float4*)(bb);
        float4 a1 = *(const float4*)(bb + 128);
        float4 a2 = *(const float4*)(bb + 256);
        float4 a3 = *(const float4*)(bb + 384);

        float c0 = a0.x * q.x + a0.y * q.y + a0.z * q.z + a0.w * q.w;
        float c1 = a1.x * q.x + a1.y * q.y + a1.z * q.z + a1.w * q.w;
        float c2 = a2.x * q.x + a2.y * q.y + a2.z * q.z + a2.w * q.w;
        float c3 = a3.x * q.x + a3.y * q.y + a3.z * q.z + a3.w * q.w;
#pragma unroll
        for (int o = 16; o > 0; o >>= 1) {
            c0 += __shfl_xor_sync(0xffffffffu, c0, o);
            c1 += __shfl_xor_sync(0xffffffffu, c1, o);
            c2 += __shfl_xor_sync(0xffffffffu, c2, o);
            c3 += __shfl_xor_sync(0xffffffffu, c3, o);
        }
        int r0 = c * 32 + wid * 4;
        float e0 = sdead[r0]     ? 0.f : expf(c0);
        float e1 = sdead[r0 + 1] ? 0.f : expf(c1);
        float e2 = sdead[r0 + 2] ? 0.f : expf(c2);
        float e3 = sdead[r0 + 3] ? 0.f : expf(c3);
        if (lane == 0) {
            sc[r0] = e0; sc[r0 + 1] = e1; sc[r0 + 2] = e2; sc[r0 + 3] = e3;
        }
        l += (e0 + e1) + (e2 + e3);
        acc.x += e0 * a0.x + e1 * a1.x + e2 * a2.x + e3 * a3.x;
        acc.y += e0 * a0.y + e1 * a1.y + e2 * a2.y + e3 * a3.y;
        acc.z += e0 * a0.z + e1 * a1.z + e2 * a2.z + e3 * a3.z;
        acc.w += e0 * a0.w + e1 * a1.w + e2 * a2.w + e3 * a3.w;
    }

    // merge 8 warps (each warp covered 4 rows per chunk; all h columns)
#pragma unroll
    for (int o = 16; o > 0; o >>= 1) l += 0.f;  // (l already full per-warp sum)
    if (lane == 0) lred[wid] = l;
    *(float4*)(accsh + wid * 132 + lane * 4) = acc;
    __syncthreads();

    float Lt = lred[0];
#pragma unroll
    for (int w = 1; w < 8; w++) Lt += lred[w];

    if (tid < HD) {
        float ssum = 0.f;
#pragma unroll
        for (int w = 0; w < 8; w++) ssum += accsh[w * 132 + tid];
        g_X[p * 2 * HD + tid] = vs[p * HD + tid];
        g_X[p * 2 * HD + HD + tid] = (Lt > 0.f) ? ssum / Lt : 0.f;
    }
    __syncthreads();

    // top-16 on unnormalized e (monotone with score): stable desc, index asc.
    if (wid == 0) {
        float val[8];
#pragma unroll
        for (int j = 0; j < 8; j++) val[j] = sc[lane + (j << 5)];
        for (int k = 0; k < KTOP; k++) {
            float bv = val[0];
            int bj = 0;
#pragma unroll
            for (int j = 1; j < 8; j++)
                if (val[j] > bv) { bv = val[j]; bj = j; }  // strict > keeps lowest index
            int bi = (bj << 5) + lane;
#pragma unroll
            for (int o = 16; o > 0; o >>= 1) {
                float ov = __shfl_xor_sync(0xffffffffu, bv, o);
                int oi = __shfl_xor_sync(0xffffffffu, bi, o);
                if (ov > bv || (ov == bv && oi < bi)) { bv = ov; bi = oi; }
            }
            if (lane == 0) g_idx[p * KTOP + k] = bi;
            if ((bi & 31) == lane) val[bi >> 5] = -1.f;  // e >= 0
        }
    }
}

// ---------------------------------------------------------------------------
// Kernel 3: register-tiled GEMM with fused top-k gather + k-loop software
// pipeline (register double buffer breaks LDS->FFMA stalls).
// Block tile BM x 128 (N) x 128 (K per split), k-chunks of 64 in smem.
// Thread tile TM x 8. block 256. BM = 16*TM.
// mode 0: A rows = vs (s=0) or gathered ve[p][idx[p][s-1]] (s>=1), W=Wfwd
// mode 1: A rows = g_X[p][128s : 128s+128], W=g_Wmod
// ---------------------------------------------------------------------------
template<int BM, int TM>
__global__ __launch_bounds__(256, 2) void gemm_kernel(const float* __restrict__ W,
                                                      const float* __restrict__ ve,
                                                      const float* __restrict__ vs,
                                                      int Kstride, int mode, int sbase) {
    extern __shared__ float smg[];
    float* As = smg;             // [64][BM] k-major
    float* Ws = smg + 64 * BM;   // [64][128] k-major

    int tid = threadIdx.x;
    int br = blockIdx.x * BM;
    int s = blockIdx.y;
    int k0 = s * 128;
    const float* Wp = (mode == 0) ? W : g_Wmod;

    constexpr int TPR = 256 / BM;       // threads per A row
    constexpr int ASPAN = 64 / TPR;     // k floats per thread per chunk
    int ar = tid / TPR;
    int akq = (tid % TPR) * ASPAN;
    const float* aptr;
    {
        int p = br + ar;
        if (mode == 0) {
            aptr = (s == 0) ? vs + (size_t)p * HD
                            : ve + ((size_t)p * NTOK + g_idx[p * KTOP + s - 1]) * HD;
        } else {
            aptr = g_X + (size_t)p * 2 * HD + k0;
        }
    }
    int wn = tid >> 1;
    int wkq = (tid & 1) * 32;
    const float* wptr = Wp + (size_t)wn * Kstride + k0;

    int tx = tid & 15;        // N-dir: cols tx*8 .. tx*8+7
    int ty = tid >> 4;        // M-dir: rows ty*TM .. ty*TM+TM-1
    float acc[TM][8];
#pragma unroll
    for (int i = 0; i < TM; i++)
#pragma unroll
        for (int j = 0; j < 8; j++) acc[i][j] = 0.f;

    float av[2][TM], wv[2][8];

    for (int c = 0; c < 2; c++) {
        int kb = c * 64;
        // Load W chunk transposed to k-major
#pragma unroll
        for (int j = 0; j < 8; j++) {
            float4 f = *(const float4*)(wptr + kb + wkq + j * 4);
            int k = wkq + j * 4;
            Ws[k * 128 + wn] = f.x;
            Ws[(k + 1) * 128 + wn] = f.y;
            Ws[(k + 2) * 128 + wn] = f.z;
            Ws[(k + 3) * 128 + wn] = f.w;
        }
        // Load A chunk (gathered rows) transposed to k-major
#pragma unroll
        for (int j = 0; j < ASPAN / 4; j++) {
            float4 f = *(const float4*)(aptr + kb + akq + j * 4);
            int k = akq + j * 4;
            As[k * BM + ar] = f.x;
            As[(k + 1) * BM + ar] = f.y;
            As[(k + 2) * BM + ar] = f.z;
            As[(k + 3) * BM + ar] = f.w;
        }
        __syncthreads();

        // preload k=0 into set 0
#pragma unroll
        for (int u = 0; u < TM / 4; u++) {
            float4 f = *(const float4*)(As + ty * TM + u * 4);
            av[0][u * 4] = f.x; av[0][u * 4 + 1] = f.y;
            av[0][u * 4 + 2] = f.z; av[0][u * 4 + 3] = f.w;
        }
        {
            float4 f0 = *(const float4*)(Ws + tx * 8);
            float4 f1 = *(const float4*)(Ws + tx * 8 + 4);
            wv[0][0] = f0.x; wv[0][1] = f0.y; wv[0][2] = f0.z; wv[0][3] = f0.w;
            wv[0][4] = f1.x; wv[0][5] = f1.y; wv[0][6] = f1.z; wv[0][7] = f1.w;
        }

#pragma unroll 4
        for (int k = 0; k < 64; k++) {
            int cur = k & 1, nxt = cur ^ 1;
            if (k < 63) {
#pragma unroll
                for (int u = 0; u < TM / 4; u++) {
                    float4 f = *(const float4*)(As + (k + 1) * BM + ty * TM + u * 4);
                    av[nxt][u * 4] = f.x; av[nxt][u * 4 + 1] = f.y;
                    av[nxt][u * 4 + 2] = f.z; av[nxt][u * 4 + 3] = f.w;
                }
                float4 f0 = *(const float4*)(Ws + (k + 1) * 128 + tx * 8);
                float4 f1 = *(const float4*)(Ws + (k + 1) * 128 + tx * 8 + 4);
                wv[nxt][0] = f0.x; wv[nxt][1] = f0.y; wv[nxt][2] = f0.z; wv[nxt][3] = f0.w;
                wv[nxt][4] = f1.x; wv[nxt][5] = f1.y; wv[nxt][6] = f1.z; wv[nxt][7] = f1.w;
            }
#pragma unroll
            for (int i = 0; i < TM; i++)
#pragma unroll
                for (int j = 0; j < 8; j++) acc[i][j] += av[cur][i] * wv[cur][j];
        }
        __syncthreads();
    }

    float* pout = g_part + (size_t)(s + sbase) * NPAIR * HD + (size_t)br * HD;
#pragma unroll
    for (int i = 0; i < TM; i++) {
        int row = ty * TM + i;
        *(float4*)(pout + row * HD + tx * 8) =
            make_float4(acc[i][0], acc[i][1], acc[i][2], acc[i][3]);
        *(float4*)(pout + row * HD + tx * 8 + 4) =
            make_float4(acc[i][4], acc[i][5], acc[i][6], acc[i][7]);
    }
}

// Fused reduce: y==0 -> v_C (17 splits, slots 0..16); y==1 -> v_M (slots 17,18)
__global__ void reduce_relu_kernel(const float* __restrict__ bfwd,
                                   const float* __restrict__ bmot,
                                   float* __restrict__ out) {
    int idx = blockIdx.x * 256 + threadIdx.x;
    if (blockIdx.y == 0) {
        float s = 0.f;
#pragma unroll
        for (int sp = 0; sp < NSPLIT1; sp++) s += g_part[(size_t)sp * NPAIR * HD + idx];
        out[idx] = fmaxf(s + bfwd[idx & (HD - 1)], 0.f);
    } else {
        float s = g_part[(size_t)17 * NPAIR * HD + idx] +
                  g_part[(size_t)18 * NPAIR * HD + idx];
        out[NPAIR * HD + idx] = fmaxf(s + bmot[idx & (HD - 1)], 0.f);
    }
}

// ---------------------------------------------------------------------------
extern "C" void kernel_launch(void* const* d_in, const int* in_sizes, int n_in,
                              void* d_out, int out_size) {
    const float* vs   = (const float*)d_in[0];
    const float* ve   = (const float*)d_in[1];
    const int*   ved  = (const int*)d_in[2];
    const float* Wq   = (const float*)d_in[3];
    const float* Wk   = (const float*)d_in[4];
    const float* Wv   = (const float*)d_in[5];
    const float* Wmot = (const float*)d_in[6];
    const float* bmot = (const float*)d_in[7];
    const float* Wfwd = (const float*)d_in[8];
    const float* bfwd = (const float*)d_in[9];
    float* out = (float*)d_out;  // [v_C_final (2048*128) | v_M_final (2048*128)]

    const int SMEM_A  = 3 * 4096 * 4;               // 48 KB attn pipeline
    const int SMEM_G1 = (64 * 128 + 64 * 128) * 4;  // 64 KB (BM=128)
    const int SMEM_G2 = (64 * 64 + 64 * 128) * 4;   // 48 KB (BM=64)
    cudaFuncSetAttribute(attn_kernel, cudaFuncAttributeMaxDynamicSharedMemorySize, SMEM_A);
    cudaFuncSetAttribute(gemm_kernel<128, 8>, cudaFuncAttributeMaxDynamicSharedMemorySize, SMEM_G1);
    cudaFuncSetAttribute(gemm_kernel<64, 4>, cudaFuncAttributeMaxDynamicSharedMemorySize, SMEM_G2);

    prep_kernel<<<dim3(128, 2), 128>>>(Wq, Wk, Wv, Wmot);
    qeff_kernel<<<256, 128>>>(vs);
    attn_kernel<<<NPAIR, 256, SMEM_A>>>(vs, ve, ved);

    // GEMM 1: [vs | gathered ve rows] @ W_fwd^T, split-K 17 -> slots 0..16
    gemm_kernel<128, 8><<<dim3(NPAIR / 128, NSPLIT1), 256, SMEM_G1>>>(Wfwd, ve, vs, 2176, 0, 0);
    // GEMM 2: X [2048,256] @ Wmod^T, split-K 2 -> slots 17,18
    gemm_kernel<64, 4><<<dim3(NPAIR / 64, 2), 256, SMEM_G2>>>(nullptr, ve, vs, 2 * HD, 1, 17);

    // Fused reduce + bias + relu for both outputs
    reduce_relu_kernel<<<dim3(NPAIR * HD / 256, 2), 256>>>(bfwd, bmot, out);
}

// round 9
// speedup vs baseline: 2.8755x; 1.2063x over previous
#include <cuda_runtime.h>
#include <cuda_bf16.h>
#include <math.h>
#include <float.h>
#include <stdint.h>

// Problem constants
#define NPAIR 2048           // B*A
#define HD 128               // H
#define NTOK 256             // N
#define KTOP 16
#define NSPLIT1 17           // 2176 / 128
#define NSLOTS 19            // 17 (gemm1) + 2 (gemm2)

// Scratch (device globals; no allocations allowed)
__device__ float g_M[HD * HD];                    // norm * Wq @ Wk^T
__device__ float g_Wmod[HD * 2 * HD];             // [Wmot(:, :128) | Wv @ Wmot(:,128:)^T]
__device__ float g_qeff[NPAIR * HD];
__device__ float g_X[NPAIR * 2 * HD];             // [vs | s_ve]
__device__ int   g_idx[NPAIR * KTOP];             // top-16 indices
__device__ float g_part[(size_t)NSLOTS * NPAIR * HD];  // split-K partials
// bf16 hi/lo weight splits
__device__ __nv_bfloat16 g_Wfh[HD * 2176];
__device__ __nv_bfloat16 g_Wfl[HD * 2176];
__device__ __nv_bfloat16 g_Wmh[HD * 256];
__device__ __nv_bfloat16 g_Wml[HD * 256];

__device__ __forceinline__ uint32_t smem_u32(const void* p) {
    uint32_t a;
    asm("{ .reg .u64 t; cvta.to.shared.u64 t, %1; cvt.u32.u64 %0, t; }" : "=r"(a) : "l"(p));
    return a;
}

// ---------------------------------------------------------------------------
// Kernel 0: build fused weight matrices. grid (128, 2), block 128
// ---------------------------------------------------------------------------
__global__ void prep_kernel(const float* __restrict__ Wq, const float* __restrict__ Wk,
                            const float* __restrict__ Wv, const float* __restrict__ Wmot) {
    __shared__ float srow[HD];
    int col = blockIdx.x;
    int t = threadIdx.x;
    if (blockIdx.y == 0) {
        srow[t] = Wk[col * HD + t];
        __syncthreads();
        const float* wq = Wq + t * HD;
        float acc = 0.f;
#pragma unroll 8
        for (int j = 0; j < HD; j++) acc += wq[j] * srow[j];
        g_M[t * HD + col] = acc * 0.08838834764831845f;  // 1/sqrt(128)
    } else {
        srow[t] = Wmot[col * 2 * HD + HD + t];
        __syncthreads();
        g_Wmod[col * 2 * HD + t] = Wmot[col * 2 * HD + t];
        const float* wv = Wv + t * HD;
        float acc = 0.f;
#pragma unroll 8
        for (int h = 0; h < HD; h++) acc += wv[h] * srow[h];
        g_Wmod[col * 2 * HD + HD + t] = acc;
    }
}

// ---------------------------------------------------------------------------
// Kernel 0b: split weights into bf16 hi/lo. Runs after prep (needs g_Wmod).
// ---------------------------------------------------------------------------
#define NWF (HD * 2176)
#define NWM (HD * 256)
__global__ void wconv_kernel(const float* __restrict__ Wfwd) {
    int i = blockIdx.x * 256 + threadIdx.x;
    if (i < NWF) {
        float w = Wfwd[i];
        __nv_bfloat16 h = __float2bfloat16_rn(w);
        g_Wfh[i] = h;
        g_Wfl[i] = __float2bfloat16_rn(w - __bfloat162float(h));
    } else if (i < NWF + NWM) {
        int j = i - NWF;
        float w = g_Wmod[j];
        __nv_bfloat16 h = __float2bfloat16_rn(w);
        g_Wmh[j] = h;
        g_Wml[j] = __float2bfloat16_rn(w - __bfloat162float(h));
    }
}

// ---------------------------------------------------------------------------
// Kernel 1: qeff[p][t] = sum_i vs[p][i] * g_M[i][t].
// grid 256, block 128; 8 pairs per block.
// ---------------------------------------------------------------------------
__global__ void qeff_kernel(const float* __restrict__ vs) {
    __shared__ float svs[8 * HD];
    int t = threadIdx.x;
    int base = blockIdx.x * 8;
    for (int k = t; k < 8 * HD; k += 128) svs[k] = vs[base * HD + k];
    __syncthreads();
    float acc[8];
#pragma unroll
    for (int p = 0; p < 8; p++) acc[p] = 0.f;
#pragma unroll 4
    for (int i = 0; i < HD; i++) {
        float m = g_M[i * HD + t];
#pragma unroll
        for (int p = 0; p < 8; p++) acc[p] += svs[p * HD + i] * m;
    }
#pragma unroll
    for (int p = 0; p < 8; p++) g_qeff[(base + p) * HD + t] = acc[p];
}

// ---------------------------------------------------------------------------
// Kernel 2: one-pass attention with cp.async triple-buffered smem pipeline.
// grid 2048, block 256, dyn smem 48 KB. (unchanged - passing at R7)
// ---------------------------------------------------------------------------
__global__ __launch_bounds__(256) void attn_kernel(const float* __restrict__ vs,
                                                   const float* __restrict__ ve,
                                                   const int* __restrict__ ved) {
    extern __shared__ float sve[];      // [3][4096] floats = 48 KB
    __shared__ float sc[NTOK];          // exp(compat)
    __shared__ float accsh[8 * 132];
    __shared__ float lred[8];
    __shared__ int sdead[NTOK];

    int tid = threadIdx.x;
    int lane = tid & 31, wid = tid >> 5;
    int p = blockIdx.x;

    sdead[tid] = ved[p * NTOK + tid];
    float4 q = *(const float4*)(g_qeff + p * HD + lane * 4);
    const float4* vb = (const float4*)(ve + (size_t)p * NTOK * HD);
    uint32_t sbase = smem_u32(sve);

    auto issue = [&](int c) {
        uint32_t d = sbase + (uint32_t)(c % 3) * 16384 + (uint32_t)tid * 16;
        const float4* src = vb + c * 1024 + tid;
#pragma unroll
        for (int j = 0; j < 4; j++) {
            asm volatile("cp.async.cg.shared.global [%0], [%1], 16;"
                         :: "r"(d + j * 4096), "l"(src + j * 256));
        }
        asm volatile("cp.async.commit_group;" ::: "memory");
    };

    issue(0);
    issue(1);

    float l = 0.f;
    float4 acc = make_float4(0.f, 0.f, 0.f, 0.f);

    for (int c = 0; c < 8; c++) {
        if (c < 7) asm volatile("cp.async.wait_group 1;" ::: "memory");
        else       asm volatile("cp.async.wait_group 0;" ::: "memory");
        __syncthreads();
        if (c < 6) issue(c + 2);

        const float* bb = sve + (c % 3) * 4096 + (wid * 4) * 128 + lane * 4;
        float4 a0 = *(const float4*)(bb);
        float4 a1 = *(const float4*)(bb + 128);
        float4 a2 = *(const float4*)(bb + 256);
        float4 a3 = *(const float4*)(bb + 384);

        float c0 = a0.x * q.x + a0.y * q.y + a0.z * q.z + a0.w * q.w;
        float c1 = a1.x * q.x + a1.y * q.y + a1.z * q.z + a1.w * q.w;
        float c2 = a2.x * q.x + a2.y * q.y + a2.z * q.z + a2.w * q.w;
        float c3 = a3.x * q.x + a3.y * q.y + a3.z * q.z + a3.w * q.w;
#pragma unroll
        for (int o = 16; o > 0; o >>= 1) {
            c0 += __shfl_xor_sync(0xffffffffu, c0, o);
            c1 += __shfl_xor_sync(0xffffffffu, c1, o);
            c2 += __shfl_xor_sync(0xffffffffu, c2, o);
            c3 += __shfl_xor_sync(0xffffffffu, c3, o);
        }
        int r0 = c * 32 + wid * 4;
        float e0 = sdead[r0]     ? 0.f : expf(c0);
        float e1 = sdead[r0 + 1] ? 0.f : expf(c1);
        float e2 = sdead[r0 + 2] ? 0.f : expf(c2);
        float e3 = sdead[r0 + 3] ? 0.f : expf(c3);
        if (lane == 0) {
            sc[r0] = e0; sc[r0 + 1] = e1; sc[r0 + 2] = e2; sc[r0 + 3] = e3;
        }
        l += (e0 + e1) + (e2 + e3);
        acc.x += e0 * a0.x + e1 * a1.x + e2 * a2.x + e3 * a3.x;
        acc.y += e0 * a0.y + e1 * a1.y + e2 * a2.y + e3 * a3.y;
        acc.z += e0 * a0.z + e1 * a1.z + e2 * a2.z + e3 * a3.z;
        acc.w += e0 * a0.w + e1 * a1.w + e2 * a2.w + e3 * a3.w;
    }

    if (lane == 0) lred[wid] = l;
    *(float4*)(accsh + wid * 132 + lane * 4) = acc;
    __syncthreads();

    float Lt = lred[0];
#pragma unroll
    for (int w = 1; w < 8; w++) Lt += lred[w];

    if (tid < HD) {
        float ssum = 0.f;
#pragma unroll
        for (int w = 0; w < 8; w++) ssum += accsh[w * 132 + tid];
        g_X[p * 2 * HD + tid] = vs[p * HD + tid];
        g_X[p * 2 * HD + HD + tid] = (Lt > 0.f) ? ssum / Lt : 0.f;
    }
    __syncthreads();

    // top-16 on unnormalized e (monotone with score): stable desc, index asc.
    if (wid == 0) {
        float val[8];
#pragma unroll
        for (int j = 0; j < 8; j++) val[j] = sc[lane + (j << 5)];
        for (int k = 0; k < KTOP; k++) {
            float bv = val[0];
            int bj = 0;
#pragma unroll
            for (int j = 1; j < 8; j++)
                if (val[j] > bv) { bv = val[j]; bj = j; }  // strict > keeps lowest index
            int bi = (bj << 5) + lane;
#pragma unroll
            for (int o = 16; o > 0; o >>= 1) {
                float ov = __shfl_xor_sync(0xffffffffu, bv, o);
                int oi = __shfl_xor_sync(0xffffffffu, bi, o);
                if (ov > bv || (ov == bv && oi < bi)) { bv = ov; bi = oi; }
            }
            if (lane == 0) g_idx[p * KTOP + k] = bi;
            if ((bi & 31) == lane) val[bi >> 5] = -1.f;  // e >= 0
        }
    }
}

// ---------------------------------------------------------------------------
// Kernel 3: bf16 tensor-core GEMM (mma.sync m16n8k16) with hi/lo fp32 recon.
// grid (16, 19): s<17 -> v_C split s (A = vs / gathered ve, W = Wfwd hi/lo);
//                s>=17 -> v_M split s-17 (A = g_X slice, W = Wmod hi/lo).
// CTA tile 128x128x128, processed as TWO sequential 64-wide k-slices.
// Per slice: smem tiles Ah/Al/Wh/Wl are [128 rows][64 bf16] with 144-byte
// row stride (18432 B each; 72 KB total -> 2 CTAs/SM).
// 8 warps (4m x 2n), warp tile 32x64.
// D = Ah*Wh + Ah*Wl + Al*Wh, fp32 accumulate (dropped lo*lo ~ 2^-18).
// ---------------------------------------------------------------------------
__global__ __launch_bounds__(256, 2) void gemm_mma_kernel(const float* __restrict__ ve,
                                                          const float* __restrict__ vs) {
    extern __shared__ char smg[];
    const uint32_t OFF_AH = 0, OFF_AL = 18432, OFF_WH = 36864, OFF_WL = 55296;
    uint32_t sb = smem_u32(smg);

    int tid = threadIdx.x;
    int lane = tid & 31, wid = tid >> 5;
    int br = blockIdx.x * 128;
    int s = blockIdx.y;
    int mode1 = (s >= NSPLIT1);
    int k0 = (mode1 ? (s - NSPLIT1) : s) * 128;
    int Kst = mode1 ? 256 : 2176;
    const __nv_bfloat16* Wh = mode1 ? g_Wmh : g_Wfh;
    const __nv_bfloat16* Wl = mode1 ? g_Wml : g_Wfl;

    // A row pointer for this thread's load row (r = tid>>1)
    int lr = tid >> 1, lh = tid & 1;   // row, half (32 k-elements each)
    const float* aptr;
    {
        int p = br + lr;
        if (!mode1) {
            aptr = (s == 0) ? vs + (size_t)p * HD
                            : ve + ((size_t)p * NTOK + g_idx[p * KTOP + s - 1]) * HD;
        } else {
            aptr = g_X + (size_t)p * 2 * HD + k0;
        }
    }
    const __nv_bfloat16* whp = Wh + (size_t)lr * Kst + k0;
    const __nv_bfloat16* wlp = Wl + (size_t)lr * Kst + k0;

    // warp tiling + ldmatrix lane addressing
    int wm = wid & 3;              // m stripe (32 rows)
    int wn = wid >> 2;             // n stripe (64 cols)
    uint32_t arow = (lane & 7) + ((lane >> 3) & 1) * 8;   // A tile row sel
    uint32_t akb  = (lane >> 4) * 16;                      // A k-byte offset
    uint32_t nrow = ((lane >> 4) & 1) * 8 + (lane & 7);    // B n-row sel
    uint32_t bkb  = ((lane >> 3) & 1) * 16;                // B k-byte offset

    float acc[2][8][4];
#pragma unroll
    for (int i = 0; i < 2; i++)
#pragma unroll
        for (int j = 0; j < 8; j++)
#pragma unroll
            for (int v = 0; v < 4; v++) acc[i][j][v] = 0.f;

    const uint32_t aoff[3] = { OFF_AH, OFF_AH, OFF_AL };
    const uint32_t woff[3] = { OFF_WH, OFF_WL, OFF_WH };

    for (int kk = 0; kk < 2; kk++) {
        // ---- load k-slice [kk*64, kk*64+64) ----
        {
            // A: 32 fp32 -> bf16 hi/lo (64 bytes each tile)
            const float4* a4 = (const float4*)(aptr + kk * 64 + lh * 32);
            char* dAh = smg + OFF_AH + lr * 144 + lh * 64;
            char* dAl = smg + OFF_AL + lr * 144 + lh * 64;
#pragma unroll
            for (int j = 0; j < 8; j++) {
                float4 f = a4[j];
                __nv_bfloat162 h0 = __floats2bfloat162_rn(f.x, f.y);
                __nv_bfloat162 h1 = __floats2bfloat162_rn(f.z, f.w);
                float2 r0 = __bfloat1622float2(h0);
                float2 r1 = __bfloat1622float2(h1);
                __nv_bfloat162 l0 = __floats2bfloat162_rn(f.x - r0.x, f.y - r0.y);
                __nv_bfloat162 l1 = __floats2bfloat162_rn(f.z - r1.x, f.w - r1.y);
                *(uint2*)(dAh + j * 8) = make_uint2(*(uint32_t*)&h0, *(uint32_t*)&h1);
                *(uint2*)(dAl + j * 8) = make_uint2(*(uint32_t*)&l0, *(uint32_t*)&l1);
            }
            // W: 32 bf16 = 64 bytes = 4 uint4 per tile
            const uint4* wh4 = (const uint4*)(whp + kk * 64 + lh * 32);
            const uint4* wl4 = (const uint4*)(wlp + kk * 64 + lh * 32);
            char* dWh = smg + OFF_WH + lr * 144 + lh * 64;
            char* dWl = smg + OFF_WL + lr * 144 + lh * 64;
#pragma unroll
            for (int j = 0; j < 4; j++) {
                *(uint4*)(dWh + j * 16) = wh4[j];
                *(uint4*)(dWl + j * 16) = wl4[j];
            }
        }
        __syncthreads();

        // ---- mma over this slice: 3 passes x 4 k16 steps ----
#pragma unroll
        for (int pass = 0; pass < 3; pass++) {
            uint32_t Ab = sb + aoff[pass] + (wm * 32 + arow) * 144 + akb;
            uint32_t Wb = sb + woff[pass] + (wn * 64 + nrow) * 144 + bkb;
#pragma unroll
            for (int ks = 0; ks < 4; ks++) {
                uint32_t a[2][4];
#pragma unroll
                for (int mt = 0; mt < 2; mt++) {
                    uint32_t ad = Ab + mt * 16 * 144 + ks * 32;
                    asm volatile("ldmatrix.sync.aligned.m8n8.x4.shared.b16 {%0,%1,%2,%3}, [%4];"
                                 : "=r"(a[mt][0]), "=r"(a[mt][1]), "=r"(a[mt][2]), "=r"(a[mt][3])
                                 : "r"(ad));
                }
                uint32_t b[4][4];
#pragma unroll
                for (int g = 0; g < 4; g++) {
                    uint32_t bd = Wb + g * 16 * 144 + ks * 32;
                    asm volatile("ldmatrix.sync.aligned.m8n8.x4.shared.b16 {%0,%1,%2,%3}, [%4];"
                                 : "=r"(b[g][0]), "=r"(b[g][1]), "=r"(b[g][2]), "=r"(b[g][3])
                                 : "r"(bd));
                }
#pragma unroll
                for (int mt = 0; mt < 2; mt++)
#pragma unroll
                    for (int nt = 0; nt < 8; nt++) {
                        uint32_t b0 = b[nt >> 1][(nt & 1) * 2];
                        uint32_t b1 = b[nt >> 1][(nt & 1) * 2 + 1];
                        asm volatile(
                            "mma.sync.aligned.m16n8k16.row.col.f32.bf16.bf16.f32 "
                            "{%0,%1,%2,%3}, {%4,%5,%6,%7}, {%8,%9}, {%0,%1,%2,%3};"
                            : "+f"(acc[mt][nt][0]), "+f"(acc[mt][nt][1]),
                              "+f"(acc[mt][nt][2]), "+f"(acc[mt][nt][3])
                            : "r"(a[mt][0]), "r"(a[mt][1]), "r"(a[mt][2]), "r"(a[mt][3]),
                              "r"(b0), "r"(b1));
                    }
            }
        }
        __syncthreads();
    }

    // ---- epilogue: fp32 accum -> g_part slot s ----
    float* pout = g_part + (size_t)s * NPAIR * HD + (size_t)br * HD;
#pragma unroll
    for (int mt = 0; mt < 2; mt++) {
        int row0 = wm * 32 + mt * 16 + (lane >> 2);
#pragma unroll
        for (int nt = 0; nt < 8; nt++) {
            int col = wn * 64 + nt * 8 + (lane & 3) * 2;
            *(float2*)(pout + (size_t)row0 * HD + col) =
                make_float2(acc[mt][nt][0], acc[mt][nt][1]);
            *(float2*)(pout + (size_t)(row0 + 8) * HD + col) =
                make_float2(acc[mt][nt][2], acc[mt][nt][3]);
        }
    }
}

// Fused reduce: y==0 -> v_C (17 splits, slots 0..16); y==1 -> v_M (slots 17,18)
__global__ void reduce_relu_kernel(const float* __restrict__ bfwd,
                                   const float* __restrict__ bmot,
                                   float* __restrict__ out) {
    int idx = blockIdx.x * 256 + threadIdx.x;
    if (blockIdx.y == 0) {
        float s = 0.f;
#pragma unroll
        for (int sp = 0; sp < NSPLIT1; sp++) s += g_part[(size_t)sp * NPAIR * HD + idx];
        out[idx] = fmaxf(s + bfwd[idx & (HD - 1)], 0.f);
    } else {
        float s = g_part[(size_t)17 * NPAIR * HD + idx] +
                  g_part[(size_t)18 * NPAIR * HD + idx];
        out[NPAIR * HD + idx] = fmaxf(s + bmot[idx & (HD - 1)], 0.f);
    }
}

// ---------------------------------------------------------------------------
extern "C" void kernel_launch(void* const* d_in, const int* in_sizes, int n_in,
                              void* d_out, int out_size) {
    const float* vs   = (const float*)d_in[0];
    const float* ve   = (const float*)d_in[1];
    const int*   ved  = (const int*)d_in[2];
    const float* Wq   = (const float*)d_in[3];
    const float* Wk   = (const float*)d_in[4];
    const float* Wv   = (const float*)d_in[5];
    const float* Wmot = (const float*)d_in[6];
    const float* bmot = (const float*)d_in[7];
    const float* Wfwd = (const float*)d_in[8];
    const float* bfwd = (const float*)d_in[9];
    float* out = (float*)d_out;  // [v_C_final (2048*128) | v_M_final (2048*128)]

    const int SMEM_A  = 3 * 4096 * 4;   // 48 KB attn pipeline
    const int SMEM_MM = 73728;          // 4 x 18432 B bf16 tiles
    cudaFuncSetAttribute(attn_kernel, cudaFuncAttributeMaxDynamicSharedMemorySize, SMEM_A);
    cudaFuncSetAttribute(gemm_mma_kernel, cudaFuncAttributeMaxDynamicSharedMemorySize, SMEM_MM);

    prep_kernel<<<dim3(128, 2), 128>>>(Wq, Wk, Wv, Wmot);
    wconv_kernel<<<(NWF + NWM + 255) / 256, 256>>>(Wfwd);
    qeff_kernel<<<256, 128>>>(vs);
    attn_kernel<<<NPAIR, 256, SMEM_A>>>(vs, ve, ved);

    // Both GEMMs in one launch: slots 0..16 (v_C splits), 17..18 (v_M splits)
    gemm_mma_kernel<<<dim3(NPAIR / 128, NSLOTS), 256, SMEM_MM>>>(ve, vs);

    // Fused reduce + bias + relu for both outputs
    reduce_relu_kernel<<<dim3(NPAIR * HD / 256, 2), 256>>>(bfwd, bmot, out);
}